// round 3
// baseline (speedup 1.0000x reference)
#include <cuda_runtime.h>
#include <cstdint>

#define B_  8
#define D_  256
#define T_  2048
#define K_  8192
#define BT_ (B_ * T_)          // 16384 rows of z_flat
#define ZQ_ELEMS (BT_ * D_)    // 4194304

// ---------------- device scratch (no allocations allowed) ----------------
__device__ unsigned long long g_best[BT_];  // packed (orderedDist<<32 | idx)
__device__ float  g_s1[BT_];                // |z_m|^2
__device__ float  g_s2[K_];                 // |c_n|^2
__device__ double g_loss;

// ---------------- init ----------------
__global__ void init_kernel() {
    int i = blockIdx.x * blockDim.x + threadIdx.x;
    if (i < BT_) g_best[i] = 0xFFFFFFFFFFFFFFFFULL;
    if (i == 0)  g_loss = 0.0;
}

// ---------------- |c|^2 : one warp per code ----------------
__global__ void s2_kernel(const float* __restrict__ cb) {
    int warp = (blockIdx.x * blockDim.x + threadIdx.x) >> 5;
    int lane = threadIdx.x & 31;
    if (warp >= K_) return;
    const float* row = cb + (size_t)warp * D_;
    double s = 0.0;
    for (int d = lane; d < D_; d += 32) { float v = row[d]; s += (double)v * v; }
    #pragma unroll
    for (int o = 16; o; o >>= 1) s += __shfl_xor_sync(0xffffffffu, s, o);
    if (lane == 0) g_s2[warp] = (float)s;
}

// ---------------- |z_m|^2 : block handles 32 rows ----------------
__global__ void s1_kernel(const float* __restrict__ z) {
    __shared__ double sm[8][33];
    int m0 = blockIdx.x * 32;
    int b  = m0 >> 11;
    int t0 = m0 & 2047;
    int tt   = threadIdx.x & 31;
    int part = threadIdx.x >> 5;
    double s = 0.0;
    #pragma unroll 4
    for (int di = 0; di < 32; di++) {
        int d = part * 32 + di;
        float v = z[((size_t)b * D_ + d) * T_ + t0 + tt];
        s += (double)v * v;
    }
    sm[part][tt] = s;
    __syncthreads();
    if (part == 0) {
        double tot = 0.0;
        #pragma unroll
        for (int p = 0; p < 8; p++) tot += sm[p][tt];
        g_s1[m0 + tt] = (float)tot;
    }
}

// ---------------- distance GEMM + fused argmin ----------------
// CTA tile 256(m) x 128(n), BK=8, 256 threads, thread tile 16x8, packed FFMA2.
#define BM 256
#define BN 128
#define BK 8
#define BNP (BN + 4)           // padded Bs row

__device__ __forceinline__ unsigned long long pack2(float v) {
    unsigned long long r;
    asm("mov.b64 %0, {%1, %1};" : "=l"(r) : "f"(v));
    return r;
}
__device__ __forceinline__ void ffma2(unsigned long long& acc,
                                      unsigned long long a,
                                      unsigned long long b) {
    asm("fma.rn.f32x2 %0, %1, %2, %0;" : "+l"(acc) : "l"(a), "l"(b));
}

__global__ void __launch_bounds__(256)
dist_argmin_kernel(const float* __restrict__ z, const float* __restrict__ cb) {
    __shared__ float As[2][BK][BM];        // [kk][m]
    __shared__ float Bs[2][BK][BNP];       // [kk][n]

    int tid = threadIdx.x;
    int tx = tid & 15;                     // n-group 0..15
    int ty = tid >> 4;                     // m-group 0..15
    int m0 = blockIdx.y * BM;              // fixed b (BM=256 divides T)
    int n0 = blockIdx.x * BN;
    int b  = m0 >> 11;
    int t0 = m0 & 2047;

    const float* zb = z + (size_t)b * D_ * T_ + t0;
    // B load mapping: thread -> (n = tid>>1, q = tid&1), loads cb[n0+n][d0+4q..+3]
    int bn = tid >> 1, bq = tid & 1;
    const float* cbp = cb + (size_t)(n0 + bn) * D_ + bq * 4;

    unsigned long long acc[16][4];
    #pragma unroll
    for (int i = 0; i < 16; i++)
        #pragma unroll
        for (int p = 0; p < 4; p++) acc[i][p] = 0ULL;

    // ---- preload stage 0 ----
    {
        #pragma unroll
        for (int j = 0; j < 2; j++) {
            int f  = tid + j * 256;        // float4 slot 0..511
            int kk = f >> 6;               // 0..7
            int m4 = f & 63;               // 0..63
            float4 v = *reinterpret_cast<const float4*>(zb + (size_t)kk * T_ + m4 * 4);
            *reinterpret_cast<float4*>(&As[0][kk][m4 * 4]) = v;
        }
        float4 v = *reinterpret_cast<const float4*>(cbp);
        Bs[0][bq * 4 + 0][bn] = v.x;
        Bs[0][bq * 4 + 1][bn] = v.y;
        Bs[0][bq * 4 + 2][bn] = v.z;
        Bs[0][bq * 4 + 3][bn] = v.w;
    }
    __syncthreads();

    int buf = 0;
    for (int d0 = 0; d0 < D_; d0 += BK) {
        bool has_next = (d0 + BK) < D_;
        float4 pa0, pa1, pb;
        if (has_next) {
            int dn = d0 + BK;
            {
                int f = tid, kk = f >> 6, m4 = f & 63;
                pa0 = *reinterpret_cast<const float4*>(zb + (size_t)(dn + kk) * T_ + m4 * 4);
            }
            {
                int f = tid + 256, kk = f >> 6, m4 = f & 63;
                pa1 = *reinterpret_cast<const float4*>(zb + (size_t)(dn + kk) * T_ + m4 * 4);
            }
            pb = *reinterpret_cast<const float4*>(cbp + dn);
        }

        #pragma unroll
        for (int kk = 0; kk < BK; kk++) {
            float ra[16];
            #pragma unroll
            for (int q = 0; q < 4; q++)
                *reinterpret_cast<float4*>(&ra[q * 4]) =
                    *reinterpret_cast<const float4*>(&As[buf][kk][ty * 16 + q * 4]);
            unsigned long long rb[4];
            {
                const ulonglong2* bp =
                    reinterpret_cast<const ulonglong2*>(&Bs[buf][kk][tx * 8]);
                ulonglong2 b01 = bp[0];
                ulonglong2 b23 = bp[1];
                rb[0] = b01.x; rb[1] = b01.y; rb[2] = b23.x; rb[3] = b23.y;
            }
            #pragma unroll
            for (int i = 0; i < 16; i++) {
                unsigned long long ra2 = pack2(ra[i]);
                ffma2(acc[i][0], ra2, rb[0]);
                ffma2(acc[i][1], ra2, rb[1]);
                ffma2(acc[i][2], ra2, rb[2]);
                ffma2(acc[i][3], ra2, rb[3]);
            }
        }

        if (has_next) {
            int nb = buf ^ 1;
            {
                int f = tid, kk = f >> 6, m4 = f & 63;
                *reinterpret_cast<float4*>(&As[nb][kk][m4 * 4]) = pa0;
            }
            {
                int f = tid + 256, kk = f >> 6, m4 = f & 63;
                *reinterpret_cast<float4*>(&As[nb][kk][m4 * 4]) = pa1;
            }
            Bs[nb][bq * 4 + 0][bn] = pb.x;
            Bs[nb][bq * 4 + 1][bn] = pb.y;
            Bs[nb][bq * 4 + 2][bn] = pb.z;
            Bs[nb][bq * 4 + 3][bn] = pb.w;
        }
        __syncthreads();
        buf ^= 1;
    }

    // Epilogue: f = fl(fl(s1 - 2*dot) + s2) exactly as reference rounding grid.
    #pragma unroll
    for (int i = 0; i < 16; i++) {
        int m = m0 + ty * 16 + i;
        float s1 = g_s1[m];
        unsigned long long best = 0xFFFFFFFFFFFFFFFFULL;
        #pragma unroll
        for (int p = 0; p < 4; p++) {
            unsigned lo32 = (unsigned)(acc[i][p] & 0xFFFFFFFFULL);
            unsigned hi32 = (unsigned)(acc[i][p] >> 32);
            float d0v = __uint_as_float(lo32);
            float d1v = __uint_as_float(hi32);
            int n = n0 + tx * 8 + p * 2;
            {
                float f = (s1 - 2.0f * d0v) + g_s2[n];
                unsigned u = __float_as_uint(f);
                u = (u & 0x80000000u) ? ~u : (u | 0x80000000u);
                unsigned long long key = ((unsigned long long)u << 32) | (unsigned)n;
                best = best < key ? best : key;
            }
            {
                float f = (s1 - 2.0f * d1v) + g_s2[n + 1];
                unsigned u = __float_as_uint(f);
                u = (u & 0x80000000u) ? ~u : (u | 0x80000000u);
                unsigned long long key = ((unsigned long long)u << 32) | (unsigned)(n + 1);
                best = best < key ? best : key;
            }
        }
        // reduce across the 16 tx lanes sharing this row (xor<16 stays in ty group)
        #pragma unroll
        for (int o = 8; o; o >>= 1) {
            unsigned long long other = __shfl_xor_sync(0xffffffffu, best, o);
            best = best < other ? best : other;
        }
        if (tx == 0) atomicMin(&g_best[m], best);
    }
}

// ---------------- gather z_q_st (transposed), indices, loss ----------------
__global__ void gather_kernel(const float* __restrict__ z,
                              const float* __restrict__ cb,
                              float* __restrict__ out, int out_size) {
    __shared__ float sm[32][257];
    __shared__ int   sidx[32];
    __shared__ double ssum[8];
    int m0 = blockIdx.x * 32;
    int b  = m0 >> 11;
    int t0 = m0 & 2047;
    int tid = threadIdx.x;

    if (tid < 32) {
        int idx = (int)(g_best[m0 + tid] & 0xFFFFFFFFULL);
        sidx[tid] = idx;
        if (out_size >= ZQ_ELEMS + BT_)
            out[ZQ_ELEMS + m0 + tid] = (float)idx;
    }
    __syncthreads();

    for (int r = 0; r < 32; r++)
        sm[r][tid] = cb[(size_t)sidx[r] * D_ + tid];
    __syncthreads();

    int tt = tid & 31;
    int dp = tid >> 5;
    double lsum = 0.0;
    #pragma unroll 4
    for (int it = 0; it < 32; it++) {
        int d = dp * 32 + it;
        size_t oi = ((size_t)b * D_ + d) * T_ + t0 + tt;
        float zq = sm[tt][d];
        float zv = z[oi];
        float r  = zq - zv;
        out[oi]  = zv + r;
        lsum += (double)r * r;
    }
    #pragma unroll
    for (int o = 16; o; o >>= 1) lsum += __shfl_xor_sync(0xffffffffu, lsum, o);
    if (tt == 0) ssum[dp] = lsum;
    __syncthreads();
    if (tid == 0) {
        double tot = 0.0;
        #pragma unroll
        for (int p = 0; p < 8; p++) tot += ssum[p];
        atomicAdd(&g_loss, tot);
    }
}

__global__ void finalize_kernel(float* __restrict__ out, int out_size) {
    if (out_size >= ZQ_ELEMS + BT_ + 1)
        out[ZQ_ELEMS + BT_] =
            (float)(1.1 * g_loss / (double)ZQ_ELEMS);
}

// ---------------- launch ----------------
extern "C" void kernel_launch(void* const* d_in, const int* in_sizes, int n_in,
                              void* d_out, int out_size) {
    const float* z  = (const float*)d_in[0];
    const float* cb = (const float*)d_in[1];
    if (n_in >= 2 && in_sizes[0] == K_ * D_ && in_sizes[1] == ZQ_ELEMS) {
        const float* t = z; z = cb; cb = t;
    }
    float* out = (float*)d_out;

    init_kernel<<<(BT_ + 255) / 256, 256>>>();
    s2_kernel<<<(K_ * 32 + 255) / 256, 256>>>(cb);
    s1_kernel<<<BT_ / 32, 256>>>(z);

    dim3 grid(K_ / BN, BT_ / BM);   // (64, 64)
    dist_argmin_kernel<<<grid, 256>>>(z, cb);

    gather_kernel<<<BT_ / 32, 256>>>(z, cb, out, out_size);
    finalize_kernel<<<1, 1>>>(out, out_size);
}

// round 5
// speedup vs baseline: 1.0074x; 1.0074x over previous
#include <cuda_runtime.h>
#include <cstdint>

#define B_  8
#define D_  256
#define T_  2048
#define K_  8192
#define BT_ (B_ * T_)
#define ZQ_ELEMS (BT_ * D_)

// ---------------- device scratch ----------------
__device__ float g_cbT[D_ * K_];            // transposed codebook [d][n]
__device__ float g_s1[BT_];
__device__ float g_s2[K_];
__device__ unsigned long long g_best[BT_];
__device__ double g_loss;

// ---------------- init ----------------
__global__ void init_kernel() {
    int i = blockIdx.x * blockDim.x + threadIdx.x;
    if (i < BT_) g_best[i] = 0xFFFFFFFFFFFFFFFFULL;
    if (i == 0)  g_loss = 0.0;
}

// ---------------- transpose codebook [K][D] -> [D][K] ----------------
__global__ void transpose_cb_kernel(const float* __restrict__ cb) {
    __shared__ float t[32][33];
    int tx = threadIdx.x & 31;
    int tg = threadIdx.x >> 5;           // 0..7
    int n0 = blockIdx.x * 32;
    int d0 = blockIdx.y * 32;
    #pragma unroll
    for (int j = 0; j < 4; j++) {
        int n = tg + 8 * j;
        t[n][tx] = cb[(size_t)(n0 + n) * D_ + d0 + tx];
    }
    __syncthreads();
    #pragma unroll
    for (int j = 0; j < 4; j++) {
        int d = tg + 8 * j;
        g_cbT[(size_t)(d0 + d) * K_ + n0 + tx] = t[tx][d];
    }
}

// ---------------- |c|^2 : one warp per row ----------------
__global__ void s2_kernel(const float* __restrict__ cb) {
    int w = threadIdx.x >> 5, lane = threadIdx.x & 31;
    int n = blockIdx.x * 8 + w;
    size_t base = (size_t)n * D_;
    double s = 0.0;
    #pragma unroll
    for (int i = 0; i < 8; i++) {
        float v = cb[base + lane + 32 * i];
        s += (double)v * v;
    }
    #pragma unroll
    for (int o = 16; o; o >>= 1) s += __shfl_xor_sync(0xffffffffu, s, o);
    if (lane == 0) g_s2[n] = (float)s;
}

// ---------------- |z_m|^2 ----------------
__global__ void s1_kernel(const float* __restrict__ z) {
    __shared__ double sm[8][33];
    int m0 = blockIdx.x * 32;
    int b  = m0 >> 11;
    int t0 = m0 & 2047;
    int tt   = threadIdx.x & 31;
    int part = threadIdx.x >> 5;
    double s = 0.0;
    #pragma unroll 4
    for (int di = 0; di < 32; di++) {
        int d = part * 32 + di;
        float v = z[((size_t)b * D_ + d) * T_ + t0 + tt];
        s += (double)v * v;
    }
    sm[part][tt] = s;
    __syncthreads();
    if (part == 0) {
        double tot = 0.0;
        #pragma unroll
        for (int p = 0; p < 8; p++) tot += sm[p][tt];
        g_s1[m0 + tt] = (float)tot;
    }
}

// ---------------- distance GEMM + fused argmin ----------------
// BM=BN=128, BK=16, 128 threads (2 CTAs/SM), thread tile 16m x 8n, FFMA2.
// Smem stored with bank-conflict-free physical permutations.
#define BMd 128
#define BNd 128
#define BKd 16

__device__ __forceinline__ unsigned long long pack2(float v) {
    unsigned long long r;
    asm("mov.b64 %0, {%1, %1};" : "=l"(r) : "f"(v));
    return r;
}
__device__ __forceinline__ void ffma2(unsigned long long& acc,
                                      unsigned long long a,
                                      unsigned long long b) {
    asm("fma.rn.f32x2 %0, %1, %2, %0;" : "+l"(acc) : "l"(a), "l"(b));
}

__global__ void __launch_bounds__(128)
dist_argmin_kernel(const float* __restrict__ z) {
    __shared__ float As[BKd * BMd];    // [kk][perm4(m4)]
    __shared__ float Bs[BKd * BNd];    // [kk][perm2(n2) pairs]

    int tid = threadIdx.x;
    int tx = tid & 15;                 // n-group (8 codes)
    int ty = tid >> 4;                 // m-group (16 rows), 0..7
    int m0 = blockIdx.y * BMd;
    int n0 = blockIdx.x * BNd;
    int b  = m0 >> 11;
    int t0 = m0 & 2047;

    const float* zb = z + (size_t)b * (D_ * T_) + t0;
    const float* bt = g_cbT + n0;

    unsigned long long acc[16][4];
    #pragma unroll
    for (int i = 0; i < 16; i++)
        #pragma unroll
        for (int p = 0; p < 4; p++) acc[i][p] = 0ULL;

    float4 pa[4], pb[4];

    // -- prefetch chunk 0 --
    #pragma unroll
    for (int j = 0; j < 4; j++) {
        int s = tid + 128 * j;
        int kk = s >> 5, x = s & 31;
        pa[j] = *reinterpret_cast<const float4*>(zb + (size_t)kk * T_ + x * 4);
        pb[j] = *reinterpret_cast<const float4*>(bt + (size_t)kk * K_ + x * 4);
    }
    // -- store chunk 0 --
    #pragma unroll
    for (int j = 0; j < 4; j++) {
        int s = tid + 128 * j;
        int kk = s >> 5, x = s & 31;
        int p4 = (x & 3) * 8 + (x >> 2);
        *reinterpret_cast<float4*>(As + kk * 128 + p4 * 4) = pa[j];
        int n2a = 2 * x, n2b = 2 * x + 1;
        int p2a = (n2a & 3) * 16 + (n2a >> 2);
        int p2b = (n2b & 3) * 16 + (n2b >> 2);
        *reinterpret_cast<float2*>(Bs + kk * 128 + p2a * 2) = make_float2(pb[j].x, pb[j].y);
        *reinterpret_cast<float2*>(Bs + kk * 128 + p2b * 2) = make_float2(pb[j].z, pb[j].w);
    }
    __syncthreads();

    for (int c = 0; c < D_ / BKd; c++) {
        // prefetch next chunk into registers
        if (c + 1 < D_ / BKd) {
            int d0 = (c + 1) * BKd;
            #pragma unroll
            for (int j = 0; j < 4; j++) {
                int s = tid + 128 * j;
                int kk = s >> 5, x = s & 31;
                pa[j] = *reinterpret_cast<const float4*>(zb + (size_t)(d0 + kk) * T_ + x * 4);
                pb[j] = *reinterpret_cast<const float4*>(bt + (size_t)(d0 + kk) * K_ + x * 4);
            }
        }
        // compute BKd k-steps from the single buffer
        #pragma unroll
        for (int kk = 0; kk < BKd; kk++) {
            float ra[16];
            #pragma unroll
            for (int q = 0; q < 4; q++)
                *reinterpret_cast<float4*>(&ra[q * 4]) =
                    *reinterpret_cast<const float4*>(As + kk * 128 + (q * 8 + ty) * 4);
            unsigned long long rb[4];
            #pragma unroll
            for (int p = 0; p < 4; p++)
                rb[p] = *reinterpret_cast<const unsigned long long*>(
                    Bs + kk * 128 + (p * 16 + tx) * 2);
            #pragma unroll
            for (int i = 0; i < 16; i++) {
                unsigned long long ra2 = pack2(ra[i]);
                ffma2(acc[i][0], ra2, rb[0]);
                ffma2(acc[i][1], ra2, rb[1]);
                ffma2(acc[i][2], ra2, rb[2]);
                ffma2(acc[i][3], ra2, rb[3]);
            }
        }
        __syncthreads();
        if (c + 1 < D_ / BKd) {
            #pragma unroll
            for (int j = 0; j < 4; j++) {
                int s = tid + 128 * j;
                int kk = s >> 5, x = s & 31;
                int p4 = (x & 3) * 8 + (x >> 2);
                *reinterpret_cast<float4*>(As + kk * 128 + p4 * 4) = pa[j];
                int n2a = 2 * x, n2b = 2 * x + 1;
                int p2a = (n2a & 3) * 16 + (n2a >> 2);
                int p2b = (n2b & 3) * 16 + (n2b >> 2);
                *reinterpret_cast<float2*>(Bs + kk * 128 + p2a * 2) = make_float2(pb[j].x, pb[j].y);
                *reinterpret_cast<float2*>(Bs + kk * 128 + p2b * 2) = make_float2(pb[j].z, pb[j].w);
            }
            __syncthreads();
        }
    }

    // Epilogue: f = fl(fl(s1 - 2*dot) + s2), reference rounding grid;
    // packed ordered key with lower-index tie-break.
    #pragma unroll
    for (int i = 0; i < 16; i++) {
        int m = m0 + ty * 16 + i;
        float s1 = g_s1[m];
        unsigned long long best = 0xFFFFFFFFFFFFFFFFULL;
        #pragma unroll
        for (int p = 0; p < 4; p++) {
            unsigned lo32 = (unsigned)(acc[i][p] & 0xFFFFFFFFULL);
            unsigned hi32 = (unsigned)(acc[i][p] >> 32);
            float d0v = __uint_as_float(lo32);
            float d1v = __uint_as_float(hi32);
            int n = n0 + tx * 8 + p * 2;
            {
                float f = (s1 - 2.0f * d0v) + g_s2[n];
                unsigned u = __float_as_uint(f);
                u = (u & 0x80000000u) ? ~u : (u | 0x80000000u);
                unsigned long long key = ((unsigned long long)u << 32) | (unsigned)n;
                best = best < key ? best : key;
            }
            {
                float f = (s1 - 2.0f * d1v) + g_s2[n + 1];
                unsigned u = __float_as_uint(f);
                u = (u & 0x80000000u) ? ~u : (u | 0x80000000u);
                unsigned long long key = ((unsigned long long)u << 32) | (unsigned)(n + 1);
                best = best < key ? best : key;
            }
        }
        #pragma unroll
        for (int o = 8; o; o >>= 1) {
            unsigned long long other = __shfl_xor_sync(0xffffffffu, best, o);
            best = best < other ? best : other;
        }
        if (tx == 0) atomicMin(&g_best[m], best);
    }
}

// ---------------- gather z_q_st, indices, loss ----------------
__global__ void gather_kernel(const float* __restrict__ z,
                              const float* __restrict__ cb,
                              float* __restrict__ out, int out_size) {
    __shared__ float sm[32][257];
    __shared__ int   sidx[32];
    __shared__ double ssum[8];
    int m0 = blockIdx.x * 32;
    int b  = m0 >> 11;
    int t0 = m0 & 2047;
    int tid = threadIdx.x;

    if (tid < 32) {
        int idx = (int)(g_best[m0 + tid] & 0xFFFFFFFFULL);
        sidx[tid] = idx;
        if (out_size >= ZQ_ELEMS + BT_)
            out[ZQ_ELEMS + m0 + tid] = (float)idx;
    }
    __syncthreads();
    for (int r = 0; r < 32; r++)
        sm[r][tid] = cb[(size_t)sidx[r] * D_ + tid];
    __syncthreads();

    int tt = tid & 31, dp = tid >> 5;
    double lsum = 0.0;
    #pragma unroll 4
    for (int it = 0; it < 32; it++) {
        int d = dp * 32 + it;
        size_t oi = ((size_t)b * D_ + d) * T_ + t0 + tt;
        float zq = sm[tt][d];
        float zv = z[oi];
        float r  = zq - zv;
        out[oi]  = zv + r;
        lsum += (double)r * r;
    }
    #pragma unroll
    for (int o = 16; o; o >>= 1) lsum += __shfl_xor_sync(0xffffffffu, lsum, o);
    if (tt == 0) ssum[dp] = lsum;
    __syncthreads();
    if (tid == 0) {
        double tot = 0.0;
        #pragma unroll
        for (int p = 0; p < 8; p++) tot += ssum[p];
        atomicAdd(&g_loss, tot);
    }
}

__global__ void finalize_kernel(float* __restrict__ out, int out_size) {
    if (out_size >= ZQ_ELEMS + BT_ + 1)
        out[ZQ_ELEMS + BT_] = (float)(1.1 * g_loss / (double)ZQ_ELEMS);
}

// ---------------- launch ----------------
extern "C" void kernel_launch(void* const* d_in, const int* in_sizes, int n_in,
                              void* d_out, int out_size) {
    const float* z  = (const float*)d_in[0];
    const float* cb = (const float*)d_in[1];
    if (n_in >= 2 && in_sizes[0] == K_ * D_ && in_sizes[1] == ZQ_ELEMS) {
        const float* t = z; z = cb; cb = t;
    }
    float* out = (float*)d_out;

    init_kernel<<<(BT_ + 255) / 256, 256>>>();
    {
        dim3 g(K_ / 32, D_ / 32);
        transpose_cb_kernel<<<g, 256>>>(cb);
    }
    s2_kernel<<<K_ / 8, 256>>>(cb);
    s1_kernel<<<BT_ / 32, 256>>>(z);

    dim3 grid(K_ / BNd, BT_ / BMd);   // (64, 128)
    dist_argmin_kernel<<<grid, 128>>>(z);

    gather_kernel<<<BT_ / 32, 256>>>(z, cb, out, out_size);
    finalize_kernel<<<1, 1>>>(out, out_size);
}

// round 6
// speedup vs baseline: 1.0645x; 1.0567x over previous
#include <cuda_runtime.h>
#include <cstdint>

#define B_  8
#define D_  256
#define T_  2048
#define K_  8192
#define BT_ (B_ * T_)
#define ZQ_ELEMS (BT_ * D_)

// ---------------- device scratch ----------------
__device__ float g_zhiT[D_ * BT_];   // [d][m] tf32 hi
__device__ float g_zloT[D_ * BT_];   // [d][m] tf32 lo
__device__ float g_chiT[D_ * K_];    // [d][n] tf32 hi
__device__ float g_cloT[D_ * K_];    // [d][n] tf32 lo
__device__ float g_s1[BT_];
__device__ float g_s2[K_];
__device__ unsigned long long g_best[BT_];
__device__ double g_loss;

__device__ __forceinline__ float tf32r(float v) {
    float r; asm("cvt.rna.tf32.f32 %0, %1;" : "=f"(r) : "f"(v)); return r;
}

// ---------------- init ----------------
__global__ void init_kernel() {
    int i = blockIdx.x * blockDim.x + threadIdx.x;
    if (i < BT_) g_best[i] = 0xFFFFFFFFFFFFFFFFULL;
    if (i == 0)  g_loss = 0.0;
}

// ------- split+transpose codebook [K][D] -> hi/lo [D][K] -------
__global__ void split_cb_kernel(const float* __restrict__ cb) {
    __shared__ float t[32][33];
    int tx = threadIdx.x & 31;
    int tg = threadIdx.x >> 5;           // 0..7
    int n0 = blockIdx.x * 32;
    int d0 = blockIdx.y * 32;
    #pragma unroll
    for (int j = 0; j < 4; j++) {
        int n = tg + 8 * j;
        t[n][tx] = cb[(size_t)(n0 + n) * D_ + d0 + tx];
    }
    __syncthreads();
    #pragma unroll
    for (int j = 0; j < 4; j++) {
        int d = tg + 8 * j;
        float v  = t[tx][d];
        float hi = tf32r(v);
        g_chiT[(size_t)(d0 + d) * K_ + n0 + tx] = hi;
        g_cloT[(size_t)(d0 + d) * K_ + n0 + tx] = tf32r(v - hi);
    }
}

// ---------------- |c|^2 : one warp per row ----------------
__global__ void s2_kernel(const float* __restrict__ cb) {
    int w = threadIdx.x >> 5, lane = threadIdx.x & 31;
    int n = blockIdx.x * 8 + w;
    size_t base = (size_t)n * D_;
    double s = 0.0;
    #pragma unroll
    for (int i = 0; i < 8; i++) {
        float v = cb[base + lane + 32 * i];
        s += (double)v * v;
    }
    #pragma unroll
    for (int o = 16; o; o >>= 1) s += __shfl_xor_sync(0xffffffffu, s, o);
    if (lane == 0) g_s2[n] = (float)s;
}

// ------- split z -> hi/lo [d][m] + s1 (32 m per block) -------
__global__ void split_z_kernel(const float* __restrict__ z) {
    __shared__ double sred[8][33];
    int m0 = blockIdx.x * 32;
    int b  = m0 >> 11;
    int t0 = m0 & 2047;
    int tt = threadIdx.x & 31;
    int dp = threadIdx.x >> 5;
    double s = 0.0;
    #pragma unroll
    for (int di = 0; di < 32; di++) {
        int d = dp * 32 + di;
        float v = z[((size_t)b * D_ + d) * T_ + t0 + tt];
        s += (double)v * v;
        float hi = tf32r(v);
        g_zhiT[(size_t)d * BT_ + m0 + tt] = hi;
        g_zloT[(size_t)d * BT_ + m0 + tt] = tf32r(v - hi);
    }
    sred[dp][tt] = s;
    __syncthreads();
    if (dp == 0) {
        double tot = 0.0;
        #pragma unroll
        for (int p = 0; p < 8; p++) tot += sred[p][tt];
        g_s1[m0 + tt] = (float)tot;
    }
}

// ---------------- dist: mma.sync tf32 3-pass + fused argmin ----------------
// CTA 128 threads = 4 warps (2m x 2n). CTA tile 64m x 128n, BK=16.
// Warp tile 32m x 64n = 2 x 8 (m16n8k8) tiles.
#define PAD_A 68
#define PAD_B 132

__device__ __forceinline__ void mma_tf32(float* c, const uint32_t* a,
                                         uint32_t b0, uint32_t b1) {
    asm volatile(
        "mma.sync.aligned.m16n8k8.row.col.f32.tf32.tf32.f32 "
        "{%0,%1,%2,%3}, {%4,%5,%6,%7}, {%8,%9}, {%0,%1,%2,%3};"
        : "+f"(c[0]), "+f"(c[1]), "+f"(c[2]), "+f"(c[3])
        : "r"(a[0]), "r"(a[1]), "r"(a[2]), "r"(a[3]), "r"(b0), "r"(b1));
}

__global__ void __launch_bounds__(128)
dist_mma_kernel() {
    __shared__ float sAh[16][PAD_A], sAl[16][PAD_A];
    __shared__ float sBh[16][PAD_B], sBl[16][PAD_B];

    int tid  = threadIdx.x;
    int wid  = tid >> 5, lane = tid & 31;
    int g    = lane >> 2;      // 0..7
    int tig  = lane & 3;       // 0..3
    int wm   = wid >> 1;       // 0..1
    int wn   = wid & 1;        // 0..1
    int m0   = blockIdx.y * 64;
    int n0   = blockIdx.x * 128;
    int mw   = wm * 32;        // warp m offset in CTA tile
    int nw   = wn * 64;        // warp n offset

    float acc[2][8][4];
    #pragma unroll
    for (int mt = 0; mt < 2; mt++)
        #pragma unroll
        for (int nt = 0; nt < 8; nt++)
            #pragma unroll
            for (int q = 0; q < 4; q++) acc[mt][nt][q] = 0.0f;

    for (int c = 0; c < D_ / 16; c++) {
        int d0 = c * 16;
        // load A tiles (16k x 64m), hi+lo: 2 float4/thread each
        #pragma unroll
        for (int j = 0; j < 2; j++) {
            int s = tid + 128 * j;
            int k = s >> 4, mq = s & 15;
            size_t go = (size_t)(d0 + k) * BT_ + m0 + mq * 4;
            *reinterpret_cast<float4*>(&sAh[k][mq * 4]) =
                *reinterpret_cast<const float4*>(g_zhiT + go);
            *reinterpret_cast<float4*>(&sAl[k][mq * 4]) =
                *reinterpret_cast<const float4*>(g_zloT + go);
        }
        // load B tiles (16k x 128n), hi+lo: 4 float4/thread each
        #pragma unroll
        for (int j = 0; j < 4; j++) {
            int s = tid + 128 * j;
            int k = s >> 5, nq = s & 31;
            size_t go = (size_t)(d0 + k) * K_ + n0 + nq * 4;
            *reinterpret_cast<float4*>(&sBh[k][nq * 4]) =
                *reinterpret_cast<const float4*>(g_chiT + go);
            *reinterpret_cast<float4*>(&sBl[k][nq * 4]) =
                *reinterpret_cast<const float4*>(g_cloT + go);
        }
        __syncthreads();

        #pragma unroll
        for (int ks = 0; ks < 16; ks += 8) {
            uint32_t ah[2][4], al[2][4];
            #pragma unroll
            for (int mt = 0; mt < 2; mt++) {
                int col = mw + mt * 16 + g;
                ah[mt][0] = __float_as_uint(sAh[ks + tig][col]);
                ah[mt][1] = __float_as_uint(sAh[ks + tig][col + 8]);
                ah[mt][2] = __float_as_uint(sAh[ks + tig + 4][col]);
                ah[mt][3] = __float_as_uint(sAh[ks + tig + 4][col + 8]);
                al[mt][0] = __float_as_uint(sAl[ks + tig][col]);
                al[mt][1] = __float_as_uint(sAl[ks + tig][col + 8]);
                al[mt][2] = __float_as_uint(sAl[ks + tig + 4][col]);
                al[mt][3] = __float_as_uint(sAl[ks + tig + 4][col + 8]);
            }
            #pragma unroll
            for (int nt = 0; nt < 8; nt++) {
                int coln = nw + nt * 8 + g;
                uint32_t bh0 = __float_as_uint(sBh[ks + tig][coln]);
                uint32_t bh1 = __float_as_uint(sBh[ks + tig + 4][coln]);
                uint32_t bl0 = __float_as_uint(sBl[ks + tig][coln]);
                uint32_t bl1 = __float_as_uint(sBl[ks + tig + 4][coln]);
                #pragma unroll
                for (int mt = 0; mt < 2; mt++) {
                    mma_tf32(acc[mt][nt], ah[mt], bh0, bh1);  // hi*hi
                    mma_tf32(acc[mt][nt], ah[mt], bl0, bl1);  // hi*lo
                    mma_tf32(acc[mt][nt], al[mt], bh0, bh1);  // lo*hi
                }
            }
        }
        __syncthreads();
    }

    // ----- epilogue: exact reference rounding + packed argmin -----
    #pragma unroll
    for (int mt = 0; mt < 2; mt++) {
        int row0 = m0 + mw + mt * 16 + g;
        int row1 = row0 + 8;
        float s1a = g_s1[row0];
        float s1b = g_s1[row1];
        unsigned long long k0 = 0xFFFFFFFFFFFFFFFFULL;
        unsigned long long k1 = 0xFFFFFFFFFFFFFFFFULL;
        #pragma unroll
        for (int nt = 0; nt < 8; nt++) {
            int nb = n0 + nw + nt * 8 + 2 * tig;
            #pragma unroll
            for (int q = 0; q < 2; q++) {
                int n = nb + q;
                float s2v = __ldg(&g_s2[n]);
                {
                    float f = (s1a - 2.0f * acc[mt][nt][q]) + s2v;
                    unsigned u = __float_as_uint(f);
                    u = (u & 0x80000000u) ? ~u : (u | 0x80000000u);
                    unsigned long long key = ((unsigned long long)u << 32) | (unsigned)n;
                    k0 = k0 < key ? k0 : key;
                }
                {
                    float f = (s1b - 2.0f * acc[mt][nt][q + 2]) + s2v;
                    unsigned u = __float_as_uint(f);
                    u = (u & 0x80000000u) ? ~u : (u | 0x80000000u);
                    unsigned long long key = ((unsigned long long)u << 32) | (unsigned)n;
                    k1 = k1 < key ? k1 : key;
                }
            }
        }
        #pragma unroll
        for (int o = 1; o <= 2; o <<= 1) {
            unsigned long long t0 = __shfl_xor_sync(0xffffffffu, k0, o);
            unsigned long long t1 = __shfl_xor_sync(0xffffffffu, k1, o);
            k0 = k0 < t0 ? k0 : t0;
            k1 = k1 < t1 ? k1 : t1;
        }
        if (tig == 0) {
            atomicMin(&g_best[row0], k0);
            atomicMin(&g_best[row1], k1);
        }
    }
}

// ---------------- gather z_q_st, indices, loss ----------------
__global__ void gather_kernel(const float* __restrict__ z,
                              const float* __restrict__ cb,
                              float* __restrict__ out, int out_size) {
    __shared__ float sm[32][257];
    __shared__ int   sidx[32];
    __shared__ double ssum[8];
    int m0 = blockIdx.x * 32;
    int b  = m0 >> 11;
    int t0 = m0 & 2047;
    int tid = threadIdx.x;

    if (tid < 32) {
        int idx = (int)(g_best[m0 + tid] & 0xFFFFFFFFULL);
        sidx[tid] = idx;
        if (out_size >= ZQ_ELEMS + BT_)
            out[ZQ_ELEMS + m0 + tid] = (float)idx;
    }
    __syncthreads();
    for (int r = 0; r < 32; r++)
        sm[r][tid] = cb[(size_t)sidx[r] * D_ + tid];
    __syncthreads();

    int tt = tid & 31, dp = tid >> 5;
    double lsum = 0.0;
    #pragma unroll 4
    for (int it = 0; it < 32; it++) {
        int d = dp * 32 + it;
        size_t oi = ((size_t)b * D_ + d) * T_ + t0 + tt;
        float zq = sm[tt][d];
        float zv = z[oi];
        float r  = zq - zv;
        out[oi]  = zv + r;
        lsum += (double)r * r;
    }
    #pragma unroll
    for (int o = 16; o; o >>= 1) lsum += __shfl_xor_sync(0xffffffffu, lsum, o);
    if (tt == 0) ssum[dp] = lsum;
    __syncthreads();
    if (tid == 0) {
        double tot = 0.0;
        #pragma unroll
        for (int p = 0; p < 8; p++) tot += ssum[p];
        atomicAdd(&g_loss, tot);
    }
}

__global__ void finalize_kernel(float* __restrict__ out, int out_size) {
    if (out_size >= ZQ_ELEMS + BT_ + 1)
        out[ZQ_ELEMS + BT_] = (float)(1.1 * g_loss / (double)ZQ_ELEMS);
}

// ---------------- launch ----------------
extern "C" void kernel_launch(void* const* d_in, const int* in_sizes, int n_in,
                              void* d_out, int out_size) {
    const float* z  = (const float*)d_in[0];
    const float* cb = (const float*)d_in[1];
    if (n_in >= 2 && in_sizes[0] == K_ * D_ && in_sizes[1] == ZQ_ELEMS) {
        const float* t = z; z = cb; cb = t;
    }
    float* out = (float*)d_out;

    init_kernel<<<(BT_ + 255) / 256, 256>>>();
    {
        dim3 g(K_ / 32, D_ / 32);
        split_cb_kernel<<<g, 256>>>(cb);
    }
    s2_kernel<<<K_ / 8, 256>>>(cb);
    split_z_kernel<<<BT_ / 32, 256>>>(z);

    dim3 grid(K_ / 128, BT_ / 64);   // (64, 256)
    dist_mma_kernel<<<grid, 128>>>();

    gather_kernel<<<BT_ / 32, 256>>>(z, cb, out, out_size);
    finalize_kernel<<<1, 1>>>(out, out_size);
}

// round 7
// speedup vs baseline: 1.3224x; 1.2423x over previous
#include <cuda_runtime.h>
#include <cstdint>

#define B_  8
#define D_  256
#define T_  2048
#define K_  8192
#define BT_ (B_ * T_)
#define ZQ_ELEMS (BT_ * D_)

// ---------------- device scratch ----------------
__device__ float g_zhiT[D_ * BT_];   // [d][m] tf32 hi
__device__ float g_zloT[D_ * BT_];   // [d][m] tf32 lo
__device__ float g_chiT[D_ * K_];    // [d][n] tf32 hi
__device__ float g_cloT[D_ * K_];    // [d][n] tf32 lo
__device__ float g_s1[BT_];
__device__ float g_s2[K_];
__device__ unsigned long long g_best[BT_];
__device__ double g_loss;

__device__ __forceinline__ float tf32r(float v) {
    float r; asm("cvt.rna.tf32.f32 %0, %1;" : "=f"(r) : "f"(v)); return r;
}

#define CP16(sa, ga) asm volatile("cp.async.cg.shared.global [%0], [%1], 16;" \
    :: "r"((uint32_t)(sa)), "l"(ga) : "memory")
#define CP_COMMIT()  asm volatile("cp.async.commit_group;" ::: "memory")

__device__ __forceinline__ uint32_t smem_u32(const void* p) {
    uint32_t a;
    asm("{ .reg .u64 t; cvta.to.shared.u64 t, %1; cvt.u32.u64 %0, t; }"
        : "=r"(a) : "l"(p));
    return a;
}

// ---------------- init ----------------
__global__ void init_kernel() {
    int i = blockIdx.x * blockDim.x + threadIdx.x;
    if (i < BT_) g_best[i] = 0xFFFFFFFFFFFFFFFFULL;
    if (i == 0)  g_loss = 0.0;
}

// ------- split+transpose codebook [K][D] -> hi/lo [D][K] -------
__global__ void split_cb_kernel(const float* __restrict__ cb) {
    __shared__ float t[32][33];
    int tx = threadIdx.x & 31;
    int tg = threadIdx.x >> 5;
    int n0 = blockIdx.x * 32;
    int d0 = blockIdx.y * 32;
    #pragma unroll
    for (int j = 0; j < 4; j++) {
        int n = tg + 8 * j;
        t[n][tx] = cb[(size_t)(n0 + n) * D_ + d0 + tx];
    }
    __syncthreads();
    #pragma unroll
    for (int j = 0; j < 4; j++) {
        int d = tg + 8 * j;
        float v  = t[tx][d];
        float hi = tf32r(v);
        g_chiT[(size_t)(d0 + d) * K_ + n0 + tx] = hi;
        g_cloT[(size_t)(d0 + d) * K_ + n0 + tx] = tf32r(v - hi);
    }
}

// ---------------- |c|^2 ----------------
__global__ void s2_kernel(const float* __restrict__ cb) {
    int w = threadIdx.x >> 5, lane = threadIdx.x & 31;
    int n = blockIdx.x * 8 + w;
    size_t base = (size_t)n * D_;
    double s = 0.0;
    #pragma unroll
    for (int i = 0; i < 8; i++) {
        float v = cb[base + lane + 32 * i];
        s += (double)v * v;
    }
    #pragma unroll
    for (int o = 16; o; o >>= 1) s += __shfl_xor_sync(0xffffffffu, s, o);
    if (lane == 0) g_s2[n] = (float)s;
}

// ------- split z -> hi/lo [d][m] + s1 -------
__global__ void split_z_kernel(const float* __restrict__ z) {
    __shared__ double sred[8][33];
    int m0 = blockIdx.x * 32;
    int b  = m0 >> 11;
    int t0 = m0 & 2047;
    int tt = threadIdx.x & 31;
    int dp = threadIdx.x >> 5;
    double s = 0.0;
    #pragma unroll
    for (int di = 0; di < 32; di++) {
        int d = dp * 32 + di;
        float v = z[((size_t)b * D_ + d) * T_ + t0 + tt];
        s += (double)v * v;
        float hi = tf32r(v);
        g_zhiT[(size_t)d * BT_ + m0 + tt] = hi;
        g_zloT[(size_t)d * BT_ + m0 + tt] = tf32r(v - hi);
    }
    sred[dp][tt] = s;
    __syncthreads();
    if (dp == 0) {
        double tot = 0.0;
        #pragma unroll
        for (int p = 0; p < 8; p++) tot += sred[p][tt];
        g_s1[m0 + tt] = (float)tot;
    }
}

// ---------------- dist: mma.sync tf32 3-pass, 256 thr, dbl-buffer ----------------
// CTA tile 128m x 128n, BK=16, 8 warps (4m x 2n), warp tile 32m x 64n.
// Pad 136 (=8 mod 32) -> conflict-free fragment LDS: bank = 8*tig + g.
#define PADW       136
#define CHF        (16 * PADW)        // floats per matrix per stage
#define STF        (4 * CHF)          // floats per stage (Ah,Al,Bh,Bl)
#define SMEM_BYTES (2 * STF * 4)

__device__ __forceinline__ void mma_tf32(float* c, const uint32_t* a,
                                         uint32_t b0, uint32_t b1) {
    asm volatile(
        "mma.sync.aligned.m16n8k8.row.col.f32.tf32.tf32.f32 "
        "{%0,%1,%2,%3}, {%4,%5,%6,%7}, {%8,%9}, {%0,%1,%2,%3};"
        : "+f"(c[0]), "+f"(c[1]), "+f"(c[2]), "+f"(c[3])
        : "r"(a[0]), "r"(a[1]), "r"(a[2]), "r"(a[3]), "r"(b0), "r"(b1));
}

__device__ __forceinline__ void issue_chunk(uint32_t sbase, int st, int c,
                                            int m0, int n0, int tid) {
    int d0 = c * 16;
    uint32_t s0 = sbase + st * (STF * 4);
    #pragma unroll
    for (int j = 0; j < 2; j++) {
        int s = tid + 256 * j;
        int k = s >> 5, q = s & 31;
        uint32_t so = (uint32_t)(k * PADW + q * 4) * 4;
        size_t ga = (size_t)(d0 + k) * BT_ + m0 + q * 4;
        CP16(s0 + so,               g_zhiT + ga);
        CP16(s0 + CHF * 4 + so,     g_zloT + ga);
        size_t gb = (size_t)(d0 + k) * K_ + n0 + q * 4;
        CP16(s0 + 2 * CHF * 4 + so, g_chiT + gb);
        CP16(s0 + 3 * CHF * 4 + so, g_cloT + gb);
    }
    CP_COMMIT();
}

__global__ void __launch_bounds__(256)
dist_mma_kernel() {
    extern __shared__ float smem[];
    uint32_t sbase = smem_u32(smem);

    int tid  = threadIdx.x;
    int wid  = tid >> 5, lane = tid & 31;
    int g    = lane >> 2;
    int tig  = lane & 3;
    int wm   = wid >> 1;       // 0..3
    int wn   = wid & 1;        // 0..1
    int m0   = blockIdx.y * 128;
    int n0   = blockIdx.x * 128;

    float acc[2][8][4];
    #pragma unroll
    for (int mt = 0; mt < 2; mt++)
        #pragma unroll
        for (int nt = 0; nt < 8; nt++)
            #pragma unroll
            for (int q = 0; q < 4; q++) acc[mt][nt][q] = 0.0f;

    issue_chunk(sbase, 0, 0, m0, n0, tid);
    issue_chunk(sbase, 1, 1, m0, n0, tid);

    for (int c = 0; c < 16; c++) {
        int st = c & 1;
        if (c < 15) asm volatile("cp.async.wait_group 1;" ::: "memory");
        else        asm volatile("cp.async.wait_group 0;" ::: "memory");
        __syncthreads();

        const float* sAh = smem + st * STF;
        const float* sAl = sAh + CHF;
        const float* sBh = sAh + 2 * CHF;
        const float* sBl = sAh + 3 * CHF;

        #pragma unroll
        for (int ks = 0; ks < 16; ks += 8) {
            uint32_t ah[2][4], al[2][4];
            #pragma unroll
            for (int mt = 0; mt < 2; mt++) {
                int col = wm * 32 + mt * 16 + g;
                int r0 = (ks + tig) * PADW, r1 = (ks + tig + 4) * PADW;
                ah[mt][0] = __float_as_uint(sAh[r0 + col]);
                ah[mt][1] = __float_as_uint(sAh[r0 + col + 8]);
                ah[mt][2] = __float_as_uint(sAh[r1 + col]);
                ah[mt][3] = __float_as_uint(sAh[r1 + col + 8]);
                al[mt][0] = __float_as_uint(sAl[r0 + col]);
                al[mt][1] = __float_as_uint(sAl[r0 + col + 8]);
                al[mt][2] = __float_as_uint(sAl[r1 + col]);
                al[mt][3] = __float_as_uint(sAl[r1 + col + 8]);
            }
            #pragma unroll
            for (int nt = 0; nt < 8; nt++) {
                int coln = wn * 64 + nt * 8 + g;
                int r0 = (ks + tig) * PADW, r1 = (ks + tig + 4) * PADW;
                uint32_t bh0 = __float_as_uint(sBh[r0 + coln]);
                uint32_t bh1 = __float_as_uint(sBh[r1 + coln]);
                uint32_t bl0 = __float_as_uint(sBl[r0 + coln]);
                uint32_t bl1 = __float_as_uint(sBl[r1 + coln]);
                #pragma unroll
                for (int mt = 0; mt < 2; mt++) {
                    mma_tf32(acc[mt][nt], ah[mt], bh0, bh1);
                    mma_tf32(acc[mt][nt], ah[mt], bl0, bl1);
                    mma_tf32(acc[mt][nt], al[mt], bh0, bh1);
                }
            }
        }
        __syncthreads();
        if (c + 2 < 16) issue_chunk(sbase, st, c + 2, m0, n0, tid);
    }

    // ----- epilogue: exact reference grid-rounding + packed argmin -----
    #pragma unroll
    for (int mt = 0; mt < 2; mt++) {
        int row0 = m0 + wm * 32 + mt * 16 + g;
        int row1 = row0 + 8;
        float s1a = g_s1[row0];
        float s1b = g_s1[row1];
        unsigned long long k0 = 0xFFFFFFFFFFFFFFFFULL;
        unsigned long long k1 = 0xFFFFFFFFFFFFFFFFULL;
        #pragma unroll
        for (int nt = 0; nt < 8; nt++) {
            int nb = n0 + wn * 64 + nt * 8 + 2 * tig;
            #pragma unroll
            for (int q = 0; q < 2; q++) {
                int n = nb + q;
                float s2v = __ldg(&g_s2[n]);
                {
                    float f = (s1a - 2.0f * acc[mt][nt][q]) + s2v;
                    unsigned u = __float_as_uint(f);
                    u = (u & 0x80000000u) ? ~u : (u | 0x80000000u);
                    unsigned long long key = ((unsigned long long)u << 32) | (unsigned)n;
                    k0 = k0 < key ? k0 : key;
                }
                {
                    float f = (s1b - 2.0f * acc[mt][nt][q + 2]) + s2v;
                    unsigned u = __float_as_uint(f);
                    u = (u & 0x80000000u) ? ~u : (u | 0x80000000u);
                    unsigned long long key = ((unsigned long long)u << 32) | (unsigned)n;
                    k1 = k1 < key ? k1 : key;
                }
            }
        }
        #pragma unroll
        for (int o = 1; o <= 2; o <<= 1) {
            unsigned long long t0 = __shfl_xor_sync(0xffffffffu, k0, o);
            unsigned long long t1 = __shfl_xor_sync(0xffffffffu, k1, o);
            k0 = k0 < t0 ? k0 : t0;
            k1 = k1 < t1 ? k1 : t1;
        }
        if (tig == 0) {
            atomicMin(&g_best[row0], k0);
            atomicMin(&g_best[row1], k1);
        }
    }
}

// ---------------- gather z_q_st, indices, loss ----------------
__global__ void gather_kernel(const float* __restrict__ z,
                              const float* __restrict__ cb,
                              float* __restrict__ out, int out_size) {
    __shared__ float sm[32][257];
    __shared__ int   sidx[32];
    __shared__ double ssum[8];
    int m0 = blockIdx.x * 32;
    int b  = m0 >> 11;
    int t0 = m0 & 2047;
    int tid = threadIdx.x;

    if (tid < 32) {
        int idx = (int)(g_best[m0 + tid] & 0xFFFFFFFFULL);
        sidx[tid] = idx;
        if (out_size >= ZQ_ELEMS + BT_)
            out[ZQ_ELEMS + m0 + tid] = (float)idx;
    }
    __syncthreads();
    for (int r = 0; r < 32; r++)
        sm[r][tid] = cb[(size_t)sidx[r] * D_ + tid];
    __syncthreads();

    int tt = tid & 31, dp = tid >> 5;
    double lsum = 0.0;
    #pragma unroll 4
    for (int it = 0; it < 32; it++) {
        int d = dp * 32 + it;
        size_t oi = ((size_t)b * D_ + d) * T_ + t0 + tt;
        float zq = sm[tt][d];
        float zv = z[oi];
        float r  = zq - zv;
        out[oi]  = zv + r;
        lsum += (double)r * r;
    }
    #pragma unroll
    for (int o = 16; o; o >>= 1) lsum += __shfl_xor_sync(0xffffffffu, lsum, o);
    if (tt == 0) ssum[dp] = lsum;
    __syncthreads();
    if (tid == 0) {
        double tot = 0.0;
        #pragma unroll
        for (int p = 0; p < 8; p++) tot += ssum[p];
        atomicAdd(&g_loss, tot);
    }
}

__global__ void finalize_kernel(float* __restrict__ out, int out_size) {
    if (out_size >= ZQ_ELEMS + BT_ + 1)
        out[ZQ_ELEMS + BT_] = (float)(1.1 * g_loss / (double)ZQ_ELEMS);
}

// ---------------- launch ----------------
extern "C" void kernel_launch(void* const* d_in, const int* in_sizes, int n_in,
                              void* d_out, int out_size) {
    const float* z  = (const float*)d_in[0];
    const float* cb = (const float*)d_in[1];
    if (n_in >= 2 && in_sizes[0] == K_ * D_ && in_sizes[1] == ZQ_ELEMS) {
        const float* t = z; z = cb; cb = t;
    }
    float* out = (float*)d_out;

    cudaFuncSetAttribute(dist_mma_kernel,
                         cudaFuncAttributeMaxDynamicSharedMemorySize, SMEM_BYTES);

    init_kernel<<<(BT_ + 255) / 256, 256>>>();
    {
        dim3 g(K_ / 32, D_ / 32);
        split_cb_kernel<<<g, 256>>>(cb);
    }
    s2_kernel<<<K_ / 8, 256>>>(cb);
    split_z_kernel<<<BT_ / 32, 256>>>(z);

    dim3 grid(K_ / 128, BT_ / 128);   // (64, 128)
    dist_mma_kernel<<<grid, 256, SMEM_BYTES>>>();

    gather_kernel<<<BT_ / 32, 256>>>(z, cb, out, out_size);
    finalize_kernel<<<1, 1>>>(out, out_size);
}

// round 8
// speedup vs baseline: 2.1431x; 1.6206x over previous
#include <cuda_runtime.h>
#include <cuda_fp16.h>
#include <cstdint>

#define B_  8
#define D_  256
#define T_  2048
#define K_  8192
#define BT_ (B_ * T_)
#define ZQ_ELEMS (BT_ * D_)

// ---------------- device scratch ----------------
__device__ __half g_zhi[BT_ * D_];   // [m][d] fp16 hi of z
__device__ __half g_zlo[BT_ * D_];   // [m][d] fp16 lo of z
__device__ __half g_chi[K_ * D_];    // [n][d] fp16 hi of 512*cb
__device__ __half g_clo[K_ * D_];    // [n][d] fp16 lo of 512*cb
__device__ float g_s1[BT_];
__device__ float g_s2[K_];
__device__ unsigned long long g_best[BT_];
__device__ double g_loss;

#define CP16(sa, ga) asm volatile("cp.async.cg.shared.global [%0], [%1], 16;" \
    :: "r"((uint32_t)(sa)), "l"(ga) : "memory")
#define CP_COMMIT()  asm volatile("cp.async.commit_group;" ::: "memory")

__device__ __forceinline__ uint32_t smem_u32(const void* p) {
    uint32_t a;
    asm("{ .reg .u64 t; cvta.to.shared.u64 t, %1; cvt.u32.u64 %0, t; }"
        : "=r"(a) : "l"(p));
    return a;
}

// ---------------- init ----------------
__global__ void init_kernel() {
    int i = blockIdx.x * blockDim.x + threadIdx.x;
    if (i < BT_) g_best[i] = 0xFFFFFFFFFFFFFFFFULL;
    if (i == 0)  g_loss = 0.0;
}

// ------- split codebook (x512) -> fp16 hi/lo [K][D] + s2; warp per row -------
__global__ void split_cb_kernel(const float* __restrict__ cb) {
    int w = threadIdx.x >> 5, lane = threadIdx.x & 31;
    int n = blockIdx.x * 8 + w;
    size_t base = (size_t)n * D_;
    double s = 0.0;
    #pragma unroll
    for (int i = 0; i < 8; i++) {
        float v = cb[base + lane + 32 * i];
        s += (double)v * v;
        float vs = v * 512.0f;                 // exact
        __half hi = __float2half_rn(vs);
        float hif = __half2float(hi);          // exact
        __half lo = __float2half_rn(vs - hif);
        g_chi[base + lane + 32 * i] = hi;
        g_clo[base + lane + 32 * i] = lo;
    }
    #pragma unroll
    for (int o = 16; o; o >>= 1) s += __shfl_xor_sync(0xffffffffu, s, o);
    if (lane == 0) g_s2[n] = (float)s;
}

// ------- split z -> fp16 hi/lo [m][d] (transpose via smem) + s1 -------
__global__ void split_z_kernel(const float* __restrict__ z) {
    __shared__ float  sz[32][257];
    __shared__ double sred[8][33];
    int m0 = blockIdx.x * 32;
    int b  = m0 >> 11;
    int t0 = m0 & 2047;
    int tt = threadIdx.x & 31;
    int dp = threadIdx.x >> 5;
    double s = 0.0;
    #pragma unroll
    for (int di = 0; di < 32; di++) {
        int d = dp * 32 + di;
        float v = z[((size_t)b * D_ + d) * T_ + t0 + tt];
        sz[tt][d] = v;
        s += (double)v * v;
    }
    sred[dp][tt] = s;
    __syncthreads();
    if (dp == 0) {
        double tot = 0.0;
        #pragma unroll
        for (int p = 0; p < 8; p++) tot += sred[p][tt];
        g_s1[m0 + tt] = (float)tot;
    }
    #pragma unroll
    for (int r8 = 0; r8 < 4; r8++) {
        int row = dp * 4 + r8;
        size_t base = (size_t)(m0 + row) * D_;
        #pragma unroll
        for (int i = 0; i < 8; i++) {
            int d = tt + 32 * i;
            float v  = sz[row][d];
            __half hi = __float2half_rn(v);
            float hif = __half2float(hi);
            __half lo = __float2half_rn(v - hif);
            g_zhi[base + d] = hi;
            g_zlo[base + d] = lo;
        }
    }
}

// ---------------- dist: fp16 mma.sync 3-pass + fused argmin ----------------
// CTA 128m x 128n, BK=32 halves, 256 thr = 8 warps (4m x 2n), warp 32m x 64n.
// smem row stride 40 halves -> all fragment ld.shared.b32 are conflict-free.
#define SROW 40
#define MATB (128 * SROW * 2)     // 10240 B per matrix per stage
#define STB  (4 * MATB)           // stage: Ah, Al, Bh, Bl
#define SMEM_BYTES (2 * STB)      // 81920

__device__ __forceinline__ void mma_fp16(float* c, const uint32_t* a,
                                         uint32_t b0, uint32_t b1) {
    asm volatile(
        "mma.sync.aligned.m16n8k16.row.col.f32.f16.f16.f32 "
        "{%0,%1,%2,%3}, {%4,%5,%6,%7}, {%8,%9}, {%0,%1,%2,%3};"
        : "+f"(c[0]), "+f"(c[1]), "+f"(c[2]), "+f"(c[3])
        : "r"(a[0]), "r"(a[1]), "r"(a[2]), "r"(a[3]), "r"(b0), "r"(b1));
}

__device__ __forceinline__ void issue_chunk(uint32_t sbase, int st, int c,
                                            int m0, int n0, int tid) {
    int d0 = c * 32;
    uint32_t s0 = sbase + st * STB;
    #pragma unroll
    for (int j = 0; j < 2; j++) {
        int seg = tid + 256 * j;
        int row = seg >> 2, q = seg & 3;
        uint32_t so = (uint32_t)(row * SROW + q * 8) * 2;
        size_t ga = (size_t)(m0 + row) * D_ + d0 + q * 8;
        CP16(s0 + so,            g_zhi + ga);
        CP16(s0 + MATB + so,     g_zlo + ga);
        size_t gb = (size_t)(n0 + row) * D_ + d0 + q * 8;
        CP16(s0 + 2 * MATB + so, g_chi + gb);
        CP16(s0 + 3 * MATB + so, g_clo + gb);
    }
    CP_COMMIT();
}

__global__ void __launch_bounds__(256)
dist_mma_kernel() {
    extern __shared__ char smem[];
    uint32_t sbase = smem_u32(smem);

    int tid  = threadIdx.x;
    int wid  = tid >> 5, lane = tid & 31;
    int g    = lane >> 2;      // 0..7
    int tig  = lane & 3;       // 0..3
    int wm   = wid >> 1;       // 0..3
    int wn   = wid & 1;        // 0..1
    int m0   = blockIdx.y * 128;
    int n0   = blockIdx.x * 128;

    float acc[2][8][4];
    #pragma unroll
    for (int mt = 0; mt < 2; mt++)
        #pragma unroll
        for (int nt = 0; nt < 8; nt++)
            #pragma unroll
            for (int q = 0; q < 4; q++) acc[mt][nt][q] = 0.0f;

    issue_chunk(sbase, 0, 0, m0, n0, tid);
    issue_chunk(sbase, 1, 1, m0, n0, tid);

    for (int c = 0; c < 8; c++) {
        int st = c & 1;
        if (c < 7) asm volatile("cp.async.wait_group 1;" ::: "memory");
        else       asm volatile("cp.async.wait_group 0;" ::: "memory");
        __syncthreads();

        const __half* sAh = (const __half*)(smem + st * STB);
        const __half* sAl = (const __half*)(smem + st * STB + MATB);
        const __half* sBh = (const __half*)(smem + st * STB + 2 * MATB);
        const __half* sBl = (const __half*)(smem + st * STB + 3 * MATB);

        #pragma unroll
        for (int ks = 0; ks < 32; ks += 16) {
            int kb = ks + 2 * tig;
            uint32_t ah[2][4], al[2][4];
            #pragma unroll
            for (int mt = 0; mt < 2; mt++) {
                int r0 = (wm * 32 + mt * 16 + g) * SROW;
                int r1 = r0 + 8 * SROW;
                ah[mt][0] = *(const uint32_t*)(sAh + r0 + kb);
                ah[mt][1] = *(const uint32_t*)(sAh + r1 + kb);
                ah[mt][2] = *(const uint32_t*)(sAh + r0 + kb + 8);
                ah[mt][3] = *(const uint32_t*)(sAh + r1 + kb + 8);
                al[mt][0] = *(const uint32_t*)(sAl + r0 + kb);
                al[mt][1] = *(const uint32_t*)(sAl + r1 + kb);
                al[mt][2] = *(const uint32_t*)(sAl + r0 + kb + 8);
                al[mt][3] = *(const uint32_t*)(sAl + r1 + kb + 8);
            }
            #pragma unroll
            for (int nt = 0; nt < 8; nt++) {
                int rn = (wn * 64 + nt * 8 + g) * SROW;
                uint32_t bh0 = *(const uint32_t*)(sBh + rn + kb);
                uint32_t bh1 = *(const uint32_t*)(sBh + rn + kb + 8);
                uint32_t bl0 = *(const uint32_t*)(sBl + rn + kb);
                uint32_t bl1 = *(const uint32_t*)(sBl + rn + kb + 8);
                #pragma unroll
                for (int mt = 0; mt < 2; mt++) {
                    mma_fp16(acc[mt][nt], ah[mt], bh0, bh1);   // hi*hi
                    mma_fp16(acc[mt][nt], ah[mt], bl0, bl1);   // hi*lo
                    mma_fp16(acc[mt][nt], al[mt], bh0, bh1);   // lo*hi
                }
            }
        }
        __syncthreads();
        if (c + 2 < 8) issue_chunk(sbase, st, c + 2, m0, n0, tid);
    }

    // ----- epilogue: acc holds 512*dot; -2*dot = fma(-2/512, acc, s1), exact
    // power-of-2 scaling -> identical rounding grid to reference.
    #pragma unroll
    for (int mt = 0; mt < 2; mt++) {
        int row0 = m0 + wm * 32 + mt * 16 + g;
        int row1 = row0 + 8;
        float s1a = g_s1[row0];
        float s1b = g_s1[row1];
        unsigned long long k0 = 0xFFFFFFFFFFFFFFFFULL;
        unsigned long long k1 = 0xFFFFFFFFFFFFFFFFULL;
        #pragma unroll
        for (int nt = 0; nt < 8; nt++) {
            int nb = n0 + wn * 64 + nt * 8 + 2 * tig;
            #pragma unroll
            for (int q = 0; q < 2; q++) {
                int n = nb + q;
                float s2v = __ldg(&g_s2[n]);
                {
                    float f = __fmaf_rn(-0.00390625f, acc[mt][nt][q], s1a) + s2v;
                    unsigned u = __float_as_uint(f);
                    u = (u & 0x80000000u) ? ~u : (u | 0x80000000u);
                    unsigned long long key = ((unsigned long long)u << 32) | (unsigned)n;
                    k0 = k0 < key ? k0 : key;
                }
                {
                    float f = __fmaf_rn(-0.00390625f, acc[mt][nt][q + 2], s1b) + s2v;
                    unsigned u = __float_as_uint(f);
                    u = (u & 0x80000000u) ? ~u : (u | 0x80000000u);
                    unsigned long long key = ((unsigned long long)u << 32) | (unsigned)n;
                    k1 = k1 < key ? k1 : key;
                }
            }
        }
        #pragma unroll
        for (int o = 1; o <= 2; o <<= 1) {
            unsigned long long t0 = __shfl_xor_sync(0xffffffffu, k0, o);
            unsigned long long t1 = __shfl_xor_sync(0xffffffffu, k1, o);
            k0 = k0 < t0 ? k0 : t0;
            k1 = k1 < t1 ? k1 : t1;
        }
        if (tig == 0) {
            atomicMin(&g_best[row0], k0);
            atomicMin(&g_best[row1], k1);
        }
    }
}

// ---------------- gather z_q_st, indices, loss ----------------
__global__ void gather_kernel(const float* __restrict__ z,
                              const float* __restrict__ cb,
                              float* __restrict__ out, int out_size) {
    __shared__ float sm[32][257];
    __shared__ int   sidx[32];
    __shared__ double ssum[8];
    int m0 = blockIdx.x * 32;
    int b  = m0 >> 11;
    int t0 = m0 & 2047;
    int tid = threadIdx.x;

    if (tid < 32) {
        int idx = (int)(g_best[m0 + tid] & 0xFFFFFFFFULL);
        sidx[tid] = idx;
        if (out_size >= ZQ_ELEMS + BT_)
            out[ZQ_ELEMS + m0 + tid] = (float)idx;
    }
    __syncthreads();
    for (int r = 0; r < 32; r++)
        sm[r][tid] = cb[(size_t)sidx[r] * D_ + tid];
    __syncthreads();

    int tt = tid & 31, dp = tid >> 5;
    double lsum = 0.0;
    #pragma unroll 4
    for (int it = 0; it < 32; it++) {
        int d = dp * 32 + it;
        size_t oi = ((size_t)b * D_ + d) * T_ + t0 + tt;
        float zq = sm[tt][d];
        float zv = z[oi];
        float r  = zq - zv;
        out[oi]  = zv + r;
        lsum += (double)r * r;
    }
    #pragma unroll
    for (int o = 16; o; o >>= 1) lsum += __shfl_xor_sync(0xffffffffu, lsum, o);
    if (tt == 0) ssum[dp] = lsum;
    __syncthreads();
    if (tid == 0) {
        double tot = 0.0;
        #pragma unroll
        for (int p = 0; p < 8; p++) tot += ssum[p];
        atomicAdd(&g_loss, tot);
    }
}

__global__ void finalize_kernel(float* __restrict__ out, int out_size) {
    if (out_size >= ZQ_ELEMS + BT_ + 1)
        out[ZQ_ELEMS + BT_] = (float)(1.1 * g_loss / (double)ZQ_ELEMS);
}

// ---------------- launch ----------------
extern "C" void kernel_launch(void* const* d_in, const int* in_sizes, int n_in,
                              void* d_out, int out_size) {
    const float* z  = (const float*)d_in[0];
    const float* cb = (const float*)d_in[1];
    if (n_in >= 2 && in_sizes[0] == K_ * D_ && in_sizes[1] == ZQ_ELEMS) {
        const float* t = z; z = cb; cb = t;
    }
    float* out = (float*)d_out;

    cudaFuncSetAttribute(dist_mma_kernel,
                         cudaFuncAttributeMaxDynamicSharedMemorySize, SMEM_BYTES);

    init_kernel<<<(BT_ + 255) / 256, 256>>>();
    split_cb_kernel<<<K_ / 8, 256>>>(cb);
    split_z_kernel<<<BT_ / 32, 256>>>(z);

    dim3 grid(K_ / 128, BT_ / 128);   // (64, 128)
    dist_mma_kernel<<<grid, 256, SMEM_BYTES>>>();

    gather_kernel<<<BT_ / 32, 256>>>(z, cb, out, out_size);
    finalize_kernel<<<1, 1>>>(out, out_size);
}

// round 9
// speedup vs baseline: 2.2647x; 1.0568x over previous
#include <cuda_runtime.h>
#include <cuda_fp16.h>
#include <cstdint>

#define B_  8
#define D_  256
#define T_  2048
#define K_  8192
#define BT_ (B_ * T_)
#define ZQ_ELEMS (BT_ * D_)

// ---------------- device scratch ----------------
__device__ __half g_zhi[BT_ * D_];   // [m][d] fp16 hi of z
__device__ __half g_zlo[BT_ * D_];   // [m][d] fp16 lo of z
__device__ __half g_chi[K_ * D_];    // [n][d] fp16 hi of 512*cb
__device__ __half g_clo[K_ * D_];    // [n][d] fp16 lo of 512*cb
__device__ float g_s1[BT_];
__device__ float g_s2[K_];
__device__ unsigned long long g_best[BT_];
__device__ double g_loss;

#define CP16(sa, ga) asm volatile("cp.async.cg.shared.global [%0], [%1], 16;" \
    :: "r"((uint32_t)(sa)), "l"(ga) : "memory")
#define CP_COMMIT()  asm volatile("cp.async.commit_group;" ::: "memory")

__device__ __forceinline__ uint32_t smem_u32(const void* p) {
    uint32_t a;
    asm("{ .reg .u64 t; cvta.to.shared.u64 t, %1; cvt.u32.u64 %0, t; }"
        : "=r"(a) : "l"(p));
    return a;
}

#define LDM4(r0, r1, r2, r3, addr) \
    asm volatile("ldmatrix.sync.aligned.m8n8.x4.shared.b16 {%0,%1,%2,%3}, [%4];" \
        : "=r"(r0), "=r"(r1), "=r"(r2), "=r"(r3) : "r"(addr))

// ---------------- init ----------------
__global__ void init_kernel() {
    int i = blockIdx.x * blockDim.x + threadIdx.x;
    if (i < BT_) g_best[i] = 0xFFFFFFFFFFFFFFFFULL;
    if (i == 0)  g_loss = 0.0;
}

// ------- split codebook (x512) -> fp16 hi/lo [K][D] + s2 -------
__global__ void split_cb_kernel(const float* __restrict__ cb) {
    int w = threadIdx.x >> 5, lane = threadIdx.x & 31;
    int n = blockIdx.x * 8 + w;
    size_t base = (size_t)n * D_;
    double s = 0.0;
    #pragma unroll
    for (int i = 0; i < 8; i++) {
        float v = cb[base + lane + 32 * i];
        s += (double)v * v;
        float vs = v * 512.0f;                 // exact
        __half hi = __float2half_rn(vs);
        float hif = __half2float(hi);          // exact
        __half lo = __float2half_rn(vs - hif);
        g_chi[base + lane + 32 * i] = hi;
        g_clo[base + lane + 32 * i] = lo;
    }
    #pragma unroll
    for (int o = 16; o; o >>= 1) s += __shfl_xor_sync(0xffffffffu, s, o);
    if (lane == 0) g_s2[n] = (float)s;
}

// ------- split z -> fp16 hi/lo [m][d] + s1 -------
__global__ void split_z_kernel(const float* __restrict__ z) {
    __shared__ float  sz[32][257];
    __shared__ double sred[8][33];
    int m0 = blockIdx.x * 32;
    int b  = m0 >> 11;
    int t0 = m0 & 2047;
    int tt = threadIdx.x & 31;
    int dp = threadIdx.x >> 5;
    double s = 0.0;
    #pragma unroll
    for (int di = 0; di < 32; di++) {
        int d = dp * 32 + di;
        float v = z[((size_t)b * D_ + d) * T_ + t0 + tt];
        sz[tt][d] = v;
        s += (double)v * v;
    }
    sred[dp][tt] = s;
    __syncthreads();
    if (dp == 0) {
        double tot = 0.0;
        #pragma unroll
        for (int p = 0; p < 8; p++) tot += sred[p][tt];
        g_s1[m0 + tt] = (float)tot;
    }
    #pragma unroll
    for (int r8 = 0; r8 < 4; r8++) {
        int row = dp * 4 + r8;
        size_t base = (size_t)(m0 + row) * D_;
        #pragma unroll
        for (int i = 0; i < 8; i++) {
            int d = tt + 32 * i;
            float v  = sz[row][d];
            __half hi = __float2half_rn(v);
            float hif = __half2float(hi);
            __half lo = __float2half_rn(v - hif);
            g_zhi[base + d] = hi;
            g_zlo[base + d] = lo;
        }
    }
}

// ---------------- dist: fp16 mma.sync 3-pass + fused argmin ----------------
// CTA 128m x 128n, BK=32, 256 thr = 8 warps (4m x 2n), warp 32m x 64n.
// ldmatrix fragment loads; pass-restructured MMAs (hh, lh, hl) to break
// accumulator dependency chains. SROW=40 -> conflict-free ldmatrix phases.
#define SROW 40
#define MATB (128 * SROW * 2)     // bytes per matrix per stage
#define STB  (4 * MATB)
#define SMEM_BYTES (2 * STB)      // 81920

__device__ __forceinline__ void mma_fp16(float* c, const uint32_t* a,
                                         uint32_t b0, uint32_t b1) {
    asm volatile(
        "mma.sync.aligned.m16n8k16.row.col.f32.f16.f16.f32 "
        "{%0,%1,%2,%3}, {%4,%5,%6,%7}, {%8,%9}, {%0,%1,%2,%3};"
        : "+f"(c[0]), "+f"(c[1]), "+f"(c[2]), "+f"(c[3])
        : "r"(a[0]), "r"(a[1]), "r"(a[2]), "r"(a[3]), "r"(b0), "r"(b1));
}

__device__ __forceinline__ void issue_chunk(uint32_t sbase, int st, int c,
                                            int m0, int n0, int tid) {
    int d0 = c * 32;
    uint32_t s0 = sbase + st * STB;
    #pragma unroll
    for (int j = 0; j < 2; j++) {
        int seg = tid + 256 * j;
        int row = seg >> 2, q = seg & 3;
        uint32_t so = (uint32_t)(row * SROW + q * 8) * 2;
        size_t ga = (size_t)(m0 + row) * D_ + d0 + q * 8;
        CP16(s0 + so,            g_zhi + ga);
        CP16(s0 + MATB + so,     g_zlo + ga);
        size_t gb = (size_t)(n0 + row) * D_ + d0 + q * 8;
        CP16(s0 + 2 * MATB + so, g_chi + gb);
        CP16(s0 + 3 * MATB + so, g_clo + gb);
    }
    CP_COMMIT();
}

__global__ void __launch_bounds__(256, 2)
dist_mma_kernel() {
    extern __shared__ char smem[];
    uint32_t sbase = smem_u32(smem);

    int tid  = threadIdx.x;
    int wid  = tid >> 5, lane = tid & 31;
    int g    = lane >> 2;      // 0..7
    int tig  = lane & 3;       // 0..3
    int wm   = wid >> 1;       // 0..3
    int wn   = wid & 1;        // 0..1
    int m0   = blockIdx.y * 128;
    int n0   = blockIdx.x * 128;

    // ldmatrix per-lane row/col offsets (in halves)
    int aRow = (lane & 7) + ((lane >> 3) & 1) * 8;   // + chunk m-offset
    int aK   = (lane >> 4) * 8;                      // chunk k-offset
    int bRow = (lane & 7) + (lane >> 4) * 8;         // + chunk n-offset
    int bK   = ((lane >> 3) & 1) * 8;

    // byte offsets within a matrix for this lane
    uint32_t offA0 = (uint32_t)((wm * 32 + aRow) * SROW + aK) * 2;        // mt=0
    uint32_t offA1 = offA0 + 16 * SROW * 2;                                // mt=1
    uint32_t offB  = (uint32_t)((wn * 64 + bRow) * SROW + bK) * 2;        // ntp=0

    float acc[2][8][4];
    #pragma unroll
    for (int mt = 0; mt < 2; mt++)
        #pragma unroll
        for (int nt = 0; nt < 8; nt++)
            #pragma unroll
            for (int q = 0; q < 4; q++) acc[mt][nt][q] = 0.0f;

    issue_chunk(sbase, 0, 0, m0, n0, tid);
    issue_chunk(sbase, 1, 1, m0, n0, tid);

    for (int c = 0; c < 8; c++) {
        int st = c & 1;
        if (c < 7) asm volatile("cp.async.wait_group 1;" ::: "memory");
        else       asm volatile("cp.async.wait_group 0;" ::: "memory");
        __syncthreads();

        uint32_t mAh = sbase + st * STB;
        uint32_t mAl = mAh + MATB;
        uint32_t mBh = mAh + 2 * MATB;
        uint32_t mBl = mAh + 3 * MATB;

        #pragma unroll
        for (int ks = 0; ks < 32; ks += 16) {
            uint32_t ksb = (uint32_t)ks * 2;
            uint32_t ah[2][4], al[2][4], bb[4][4];
            // A fragments (hi, lo)
            LDM4(ah[0][0], ah[0][1], ah[0][2], ah[0][3], mAh + offA0 + ksb);
            LDM4(ah[1][0], ah[1][1], ah[1][2], ah[1][3], mAh + offA1 + ksb);
            LDM4(al[0][0], al[0][1], al[0][2], al[0][3], mAl + offA0 + ksb);
            LDM4(al[1][0], al[1][1], al[1][2], al[1][3], mAl + offA1 + ksb);
            // B hi fragments: 4 nt-pairs
            #pragma unroll
            for (int p = 0; p < 4; p++)
                LDM4(bb[p][0], bb[p][1], bb[p][2], bb[p][3],
                     mBh + offB + (uint32_t)(p * 16 * SROW) * 2 + ksb);
            // pass 1: hi*hi
            #pragma unroll
            for (int p = 0; p < 4; p++) {
                mma_fp16(acc[0][2 * p],     ah[0], bb[p][0], bb[p][1]);
                mma_fp16(acc[1][2 * p],     ah[1], bb[p][0], bb[p][1]);
                mma_fp16(acc[0][2 * p + 1], ah[0], bb[p][2], bb[p][3]);
                mma_fp16(acc[1][2 * p + 1], ah[1], bb[p][2], bb[p][3]);
            }
            // pass 2: lo*hi (reuse B hi)
            #pragma unroll
            for (int p = 0; p < 4; p++) {
                mma_fp16(acc[0][2 * p],     al[0], bb[p][0], bb[p][1]);
                mma_fp16(acc[1][2 * p],     al[1], bb[p][0], bb[p][1]);
                mma_fp16(acc[0][2 * p + 1], al[0], bb[p][2], bb[p][3]);
                mma_fp16(acc[1][2 * p + 1], al[1], bb[p][2], bb[p][3]);
            }
            // B lo fragments
            #pragma unroll
            for (int p = 0; p < 4; p++)
                LDM4(bb[p][0], bb[p][1], bb[p][2], bb[p][3],
                     mBl + offB + (uint32_t)(p * 16 * SROW) * 2 + ksb);
            // pass 3: hi*lo
            #pragma unroll
            for (int p = 0; p < 4; p++) {
                mma_fp16(acc[0][2 * p],     ah[0], bb[p][0], bb[p][1]);
                mma_fp16(acc[1][2 * p],     ah[1], bb[p][0], bb[p][1]);
                mma_fp16(acc[0][2 * p + 1], ah[0], bb[p][2], bb[p][3]);
                mma_fp16(acc[1][2 * p + 1], ah[1], bb[p][2], bb[p][3]);
            }
        }
        __syncthreads();
        if (c + 2 < 8) issue_chunk(sbase, st, c + 2, m0, n0, tid);
    }

    // ----- epilogue: acc = 512*dot; exact /512 via fma; reference grid -----
    #pragma unroll
    for (int mt = 0; mt < 2; mt++) {
        int row0 = m0 + wm * 32 + mt * 16 + g;
        int row1 = row0 + 8;
        float s1a = g_s1[row0];
        float s1b = g_s1[row1];
        unsigned long long k0 = 0xFFFFFFFFFFFFFFFFULL;
        unsigned long long k1 = 0xFFFFFFFFFFFFFFFFULL;
        #pragma unroll
        for (int nt = 0; nt < 8; nt++) {
            int nb = n0 + wn * 64 + nt * 8 + 2 * tig;
            #pragma unroll
            for (int q = 0; q < 2; q++) {
                int n = nb + q;
                float s2v = __ldg(&g_s2[n]);
                {
                    float f = __fmaf_rn(-0.00390625f, acc[mt][nt][q], s1a) + s2v;
                    unsigned u = __float_as_uint(f);
                    u = (u & 0x80000000u) ? ~u : (u | 0x80000000u);
                    unsigned long long key = ((unsigned long long)u << 32) | (unsigned)n;
                    k0 = k0 < key ? k0 : key;
                }
                {
                    float f = __fmaf_rn(-0.00390625f, acc[mt][nt][q + 2], s1b) + s2v;
                    unsigned u = __float_as_uint(f);
                    u = (u & 0x80000000u) ? ~u : (u | 0x80000000u);
                    unsigned long long key = ((unsigned long long)u << 32) | (unsigned)n;
                    k1 = k1 < key ? k1 : key;
                }
            }
        }
        #pragma unroll
        for (int o = 1; o <= 2; o <<= 1) {
            unsigned long long t0 = __shfl_xor_sync(0xffffffffu, k0, o);
            unsigned long long t1 = __shfl_xor_sync(0xffffffffu, k1, o);
            k0 = k0 < t0 ? k0 : t0;
            k1 = k1 < t1 ? k1 : t1;
        }
        if (tig == 0) {
            atomicMin(&g_best[row0], k0);
            atomicMin(&g_best[row1], k1);
        }
    }
}

// ---------------- gather z_q_st, indices, loss ----------------
__global__ void gather_kernel(const float* __restrict__ z,
                              const float* __restrict__ cb,
                              float* __restrict__ out, int out_size) {
    __shared__ float sm[32][257];
    __shared__ int   sidx[32];
    __shared__ double ssum[8];
    int m0 = blockIdx.x * 32;
    int b  = m0 >> 11;
    int t0 = m0 & 2047;
    int tid = threadIdx.x;

    if (tid < 32) {
        int idx = (int)(g_best[m0 + tid] & 0xFFFFFFFFULL);
        sidx[tid] = idx;
        if (out_size >= ZQ_ELEMS + BT_)
            out[ZQ_ELEMS + m0 + tid] = (float)idx;
    }
    __syncthreads();
    for (int r = 0; r < 32; r++)
        sm[r][tid] = cb[(size_t)sidx[r] * D_ + tid];
    __syncthreads();

    int tt = tid & 31, dp = tid >> 5;
    double lsum = 0.0;
    #pragma unroll 4
    for (int it = 0; it < 32; it++) {
        int d = dp * 32 + it;
        size_t oi = ((size_t)b * D_ + d) * T_ + t0 + tt;
        float zq = sm[tt][d];
        float zv = z[oi];
        float r  = zq - zv;
        out[oi]  = zv + r;
        lsum += (double)r * r;
    }
    #pragma unroll
    for (int o = 16; o; o >>= 1) lsum += __shfl_xor_sync(0xffffffffu, lsum, o);
    if (tt == 0) ssum[dp] = lsum;
    __syncthreads();
    if (tid == 0) {
        double tot = 0.0;
        #pragma unroll
        for (int p = 0; p < 8; p++) tot += ssum[p];
        atomicAdd(&g_loss, tot);
    }
}

__global__ void finalize_kernel(float* __restrict__ out, int out_size) {
    if (out_size >= ZQ_ELEMS + BT_ + 1)
        out[ZQ_ELEMS + BT_] = (float)(1.1 * g_loss / (double)ZQ_ELEMS);
}

// ---------------- launch ----------------
extern "C" void kernel_launch(void* const* d_in, const int* in_sizes, int n_in,
                              void* d_out, int out_size) {
    const float* z  = (const float*)d_in[0];
    const float* cb = (const float*)d_in[1];
    if (n_in >= 2 && in_sizes[0] == K_ * D_ && in_sizes[1] == ZQ_ELEMS) {
        const float* t = z; z = cb; cb = t;
    }
    float* out = (float*)d_out;

    cudaFuncSetAttribute(dist_mma_kernel,
                         cudaFuncAttributeMaxDynamicSharedMemorySize, SMEM_BYTES);

    init_kernel<<<(BT_ + 255) / 256, 256>>>();
    split_cb_kernel<<<K_ / 8, 256>>>(cb);
    split_z_kernel<<<BT_ / 32, 256>>>(z);

    dim3 grid(K_ / 128, BT_ / 128);   // (64, 128)
    dist_mma_kernel<<<grid, 256, SMEM_BYTES>>>();

    gather_kernel<<<BT_ / 32, 256>>>(z, cb, out, out_size);
    finalize_kernel<<<1, 1>>>(out, out_size);
}

// round 10
// speedup vs baseline: 2.3008x; 1.0159x over previous
#include <cuda_runtime.h>
#include <cuda_fp16.h>
#include <cstdint>

#define B_  8
#define D_  256
#define T_  2048
#define K_  8192
#define BT_ (B_ * T_)
#define ZQ_ELEMS (BT_ * D_)

// ---------------- device scratch ----------------
__device__ __half g_zhi[BT_ * D_];   // [m][d] fp16 hi of z
__device__ __half g_zlo[BT_ * D_];   // [m][d] fp16 lo of z
__device__ __half g_chi[K_ * D_];    // [n][d] fp16 hi of 512*cb
__device__ __half g_clo[K_ * D_];    // [n][d] fp16 lo of 512*cb
__device__ float g_s1[BT_];
__device__ float g_s2[K_];
__device__ unsigned long long g_best[BT_];
__device__ double g_loss;

#define CP16(sa, ga) asm volatile("cp.async.cg.shared.global [%0], [%1], 16;" \
    :: "r"((uint32_t)(sa)), "l"(ga) : "memory")
#define CP_COMMIT()  asm volatile("cp.async.commit_group;" ::: "memory")

__device__ __forceinline__ uint32_t smem_u32(const void* p) {
    uint32_t a;
    asm("{ .reg .u64 t; cvta.to.shared.u64 t, %1; cvt.u32.u64 %0, t; }"
        : "=r"(a) : "l"(p));
    return a;
}

#define LDM4(r, addr) \
    asm volatile("ldmatrix.sync.aligned.m8n8.x4.shared.b16 {%0,%1,%2,%3}, [%4];" \
        : "=r"((r)[0]), "=r"((r)[1]), "=r"((r)[2]), "=r"((r)[3]) : "r"(addr))

// ---------------- init ----------------
__global__ void init_kernel() {
    int i = blockIdx.x * blockDim.x + threadIdx.x;
    if (i < BT_) g_best[i] = 0xFFFFFFFFFFFFFFFFULL;
    if (i == 0)  g_loss = 0.0;
}

// ------- split codebook (x512) -> fp16 hi/lo [K][D] + s2 -------
__global__ void split_cb_kernel(const float* __restrict__ cb) {
    int w = threadIdx.x >> 5, lane = threadIdx.x & 31;
    int n = blockIdx.x * 8 + w;
    size_t base = (size_t)n * D_;
    double s = 0.0;
    #pragma unroll
    for (int i = 0; i < 8; i++) {
        float v = cb[base + lane + 32 * i];
        s += (double)v * v;
        float vs = v * 512.0f;                 // exact
        __half hi = __float2half_rn(vs);
        float hif = __half2float(hi);          // exact
        __half lo = __float2half_rn(vs - hif);
        g_chi[base + lane + 32 * i] = hi;
        g_clo[base + lane + 32 * i] = lo;
    }
    #pragma unroll
    for (int o = 16; o; o >>= 1) s += __shfl_xor_sync(0xffffffffu, s, o);
    if (lane == 0) g_s2[n] = (float)s;
}

// ------- split z -> fp16 hi/lo [m][d] + s1 -------
__global__ void split_z_kernel(const float* __restrict__ z) {
    __shared__ float  sz[32][257];
    __shared__ double sred[8][33];
    int m0 = blockIdx.x * 32;
    int b  = m0 >> 11;
    int t0 = m0 & 2047;
    int tt = threadIdx.x & 31;
    int dp = threadIdx.x >> 5;
    double s = 0.0;
    #pragma unroll
    for (int di = 0; di < 32; di++) {
        int d = dp * 32 + di;
        float v = z[((size_t)b * D_ + d) * T_ + t0 + tt];
        sz[tt][d] = v;
        s += (double)v * v;
    }
    sred[dp][tt] = s;
    __syncthreads();
    if (dp == 0) {
        double tot = 0.0;
        #pragma unroll
        for (int p = 0; p < 8; p++) tot += sred[p][tt];
        g_s1[m0 + tt] = (float)tot;
    }
    #pragma unroll
    for (int r8 = 0; r8 < 4; r8++) {
        int row = dp * 4 + r8;
        size_t base = (size_t)(m0 + row) * D_;
        #pragma unroll
        for (int i = 0; i < 8; i++) {
            int d = tt + 32 * i;
            float v  = sz[row][d];
            __half hi = __float2half_rn(v);
            float hif = __half2float(hi);
            __half lo = __float2half_rn(v - hif);
            g_zhi[base + d] = hi;
            g_zlo[base + d] = lo;
        }
    }
}

// ---------------- dist: fp16 mma.sync 3-pass + fused argmin ----------------
#define SROW 40
#define MATB (128 * SROW * 2)
#define STB  (4 * MATB)
#define SMEM_BYTES (2 * STB)      // 81920

// mma: NON-volatile (pure reg op) so ptxas can schedule around ldmatrix.
__device__ __forceinline__ void mma_fp16(float* c, const uint32_t* a,
                                         uint32_t b0, uint32_t b1) {
    asm("mma.sync.aligned.m16n8k16.row.col.f32.f16.f16.f32 "
        "{%0,%1,%2,%3}, {%4,%5,%6,%7}, {%8,%9}, {%0,%1,%2,%3};"
        : "+f"(c[0]), "+f"(c[1]), "+f"(c[2]), "+f"(c[3])
        : "r"(a[0]), "r"(a[1]), "r"(a[2]), "r"(a[3]), "r"(b0), "r"(b1));
}

__global__ void __launch_bounds__(256, 2)
dist_mma_kernel() {
    extern __shared__ char smem[];
    uint32_t sbase = smem_u32(smem);

    int tid  = threadIdx.x;
    int wid  = tid >> 5, lane = tid & 31;
    int g    = lane >> 2;
    int tig  = lane & 3;
    int wm   = wid >> 1;       // 0..3
    int wn   = wid & 1;        // 0..1
    int m0   = blockIdx.y * 128;
    int n0   = blockIdx.x * 128;

    // ldmatrix lane offsets
    int aRow = (lane & 7) + ((lane >> 3) & 1) * 8;
    int aK   = (lane >> 4) * 8;
    int bRow = (lane & 7) + (lane >> 4) * 8;
    int bK   = ((lane >> 3) & 1) * 8;
    uint32_t offA0 = (uint32_t)((wm * 32 + aRow) * SROW + aK) * 2;
    uint32_t offA1 = offA0 + 16 * SROW * 2;
    uint32_t offB  = (uint32_t)((wn * 64 + bRow) * SROW + bK) * 2;

    // precomputed cp.async source pointers (chunk 0) and smem offsets
    int srow = tid >> 2, sq = tid & 3;
    uint32_t so0 = (uint32_t)(srow * SROW + sq * 8) * 2;
    uint32_t so1 = (uint32_t)((srow + 64) * SROW + sq * 8) * 2;
    const __half* pA0 = g_zhi + (size_t)(m0 + srow) * D_ + sq * 8;
    const __half* pA1 = g_zhi + (size_t)(m0 + srow + 64) * D_ + sq * 8;
    const __half* pB0 = g_chi + (size_t)(n0 + srow) * D_ + sq * 8;
    const __half* pB1 = g_chi + (size_t)(n0 + srow + 64) * D_ + sq * 8;
    const ptrdiff_t LOO = (ptrdiff_t)BT_ * D_;   // hi->lo offset (z)
    const ptrdiff_t LOC = (ptrdiff_t)K_ * D_;    // hi->lo offset (cb)

    float acc[2][8][4];
    #pragma unroll
    for (int mt = 0; mt < 2; mt++)
        #pragma unroll
        for (int nt = 0; nt < 8; nt++)
            #pragma unroll
            for (int q = 0; q < 4; q++) acc[mt][nt][q] = 0.0f;

    #define ISSUE_CHUNK(st, c) do {                                          \
        uint32_t s0 = sbase + (st) * STB;                                     \
        int dd = (c) * 32;                                                    \
        CP16(s0 + so0,            pA0 + dd);                                  \
        CP16(s0 + so1,            pA1 + dd);                                  \
        CP16(s0 + MATB + so0,     pA0 + LOO + dd);                            \
        CP16(s0 + MATB + so1,     pA1 + LOO + dd);                            \
        CP16(s0 + 2 * MATB + so0, pB0 + dd);                                  \
        CP16(s0 + 2 * MATB + so1, pB1 + dd);                                  \
        CP16(s0 + 3 * MATB + so0, pB0 + LOC + dd);                            \
        CP16(s0 + 3 * MATB + so1, pB1 + LOC + dd);                            \
        CP_COMMIT();                                                          \
    } while (0)

    ISSUE_CHUNK(0, 0);
    ISSUE_CHUNK(1, 1);

    for (int c = 0; c < 8; c++) {
        int st = c & 1;
        if (c < 7) asm volatile("cp.async.wait_group 1;" ::: "memory");
        else       asm volatile("cp.async.wait_group 0;" ::: "memory");
        __syncthreads();

        uint32_t mAh = sbase + st * STB;
        uint32_t mAl = mAh + MATB;
        uint32_t mBh = mAh + 2 * MATB;
        uint32_t mBl = mAh + 3 * MATB;

        #pragma unroll
        for (int ks = 0; ks < 32; ks += 16) {
            uint32_t ksb = (uint32_t)ks * 2;
            uint32_t ah[2][4], al[2][4], bb[4][4];

            // B-hi (4) + A-hi (2) up front
            #pragma unroll
            for (int p = 0; p < 4; p++)
                LDM4(bb[p], mBh + offB + (uint32_t)(p * 16 * SROW) * 2 + ksb);
            LDM4(ah[0], mAh + offA0 + ksb);
            LDM4(ah[1], mAh + offA1 + ksb);

            // pass 1: hi*hi; interleave A-lo loads (consumed in pass 2)
            mma_fp16(acc[0][0], ah[0], bb[0][0], bb[0][1]);
            mma_fp16(acc[1][0], ah[1], bb[0][0], bb[0][1]);
            mma_fp16(acc[0][1], ah[0], bb[0][2], bb[0][3]);
            mma_fp16(acc[1][1], ah[1], bb[0][2], bb[0][3]);
            LDM4(al[0], mAl + offA0 + ksb);
            mma_fp16(acc[0][2], ah[0], bb[1][0], bb[1][1]);
            mma_fp16(acc[1][2], ah[1], bb[1][0], bb[1][1]);
            mma_fp16(acc[0][3], ah[0], bb[1][2], bb[1][3]);
            mma_fp16(acc[1][3], ah[1], bb[1][2], bb[1][3]);
            LDM4(al[1], mAl + offA1 + ksb);
            #pragma unroll
            for (int p = 2; p < 4; p++) {
                mma_fp16(acc[0][2 * p],     ah[0], bb[p][0], bb[p][1]);
                mma_fp16(acc[1][2 * p],     ah[1], bb[p][0], bb[p][1]);
                mma_fp16(acc[0][2 * p + 1], ah[0], bb[p][2], bb[p][3]);
                mma_fp16(acc[1][2 * p + 1], ah[1], bb[p][2], bb[p][3]);
            }

            // pass 2: lo*hi; after last use of Bh[p], overwrite with B-lo[p]
            #pragma unroll
            for (int p = 0; p < 4; p++) {
                mma_fp16(acc[0][2 * p],     al[0], bb[p][0], bb[p][1]);
                mma_fp16(acc[1][2 * p],     al[1], bb[p][0], bb[p][1]);
                mma_fp16(acc[0][2 * p + 1], al[0], bb[p][2], bb[p][3]);
                mma_fp16(acc[1][2 * p + 1], al[1], bb[p][2], bb[p][3]);
                LDM4(bb[p], mBl + offB + (uint32_t)(p * 16 * SROW) * 2 + ksb);
            }

            // pass 3: hi*lo
            #pragma unroll
            for (int p = 0; p < 4; p++) {
                mma_fp16(acc[0][2 * p],     ah[0], bb[p][0], bb[p][1]);
                mma_fp16(acc[1][2 * p],     ah[1], bb[p][0], bb[p][1]);
                mma_fp16(acc[0][2 * p + 1], ah[0], bb[p][2], bb[p][3]);
                mma_fp16(acc[1][2 * p + 1], ah[1], bb[p][2], bb[p][3]);
            }
        }
        __syncthreads();
        if (c + 2 < 8) ISSUE_CHUNK(st, c + 2);
    }

    // ----- epilogue: acc = 512*dot; exact /512 via fma; reference grid -----
    #pragma unroll
    for (int mt = 0; mt < 2; mt++) {
        int row0 = m0 + wm * 32 + mt * 16 + g;
        int row1 = row0 + 8;
        float s1a = g_s1[row0];
        float s1b = g_s1[row1];
        unsigned long long k0 = 0xFFFFFFFFFFFFFFFFULL;
        unsigned long long k1 = 0xFFFFFFFFFFFFFFFFULL;
        #pragma unroll
        for (int nt = 0; nt < 8; nt++) {
            int nb = n0 + wn * 64 + nt * 8 + 2 * tig;
            #pragma unroll
            for (int q = 0; q < 2; q++) {
                int n = nb + q;
                float s2v = __ldg(&g_s2[n]);
                {
                    float f = __fmaf_rn(-0.00390625f, acc[mt][nt][q], s1a) + s2v;
                    unsigned u = __float_as_uint(f);
                    u = (u & 0x80000000u) ? ~u : (u | 0x80000000u);
                    unsigned long long key = ((unsigned long long)u << 32) | (unsigned)n;
                    k0 = k0 < key ? k0 : key;
                }
                {
                    float f = __fmaf_rn(-0.00390625f, acc[mt][nt][q + 2], s1b) + s2v;
                    unsigned u = __float_as_uint(f);
                    u = (u & 0x80000000u) ? ~u : (u | 0x80000000u);
                    unsigned long long key = ((unsigned long long)u << 32) | (unsigned)n;
                    k1 = k1 < key ? k1 : key;
                }
            }
        }
        #pragma unroll
        for (int o = 1; o <= 2; o <<= 1) {
            unsigned long long t0 = __shfl_xor_sync(0xffffffffu, k0, o);
            unsigned long long t1 = __shfl_xor_sync(0xffffffffu, k1, o);
            k0 = k0 < t0 ? k0 : t0;
            k1 = k1 < t1 ? k1 : t1;
        }
        if (tig == 0) {
            atomicMin(&g_best[row0], k0);
            atomicMin(&g_best[row1], k1);
        }
    }
}

// ---------------- gather z_q_st, indices, loss ----------------
__global__ void gather_kernel(const float* __restrict__ z,
                              const float* __restrict__ cb,
                              float* __restrict__ out, int out_size) {
    __shared__ float sm[32][257];
    __shared__ int   sidx[32];
    __shared__ double ssum[8];
    int m0 = blockIdx.x * 32;
    int b  = m0 >> 11;
    int t0 = m0 & 2047;
    int tid = threadIdx.x;

    if (tid < 32) {
        int idx = (int)(g_best[m0 + tid] & 0xFFFFFFFFULL);
        sidx[tid] = idx;
        if (out_size >= ZQ_ELEMS + BT_)
            out[ZQ_ELEMS + m0 + tid] = (float)idx;
    }
    __syncthreads();
    for (int r = 0; r < 32; r++)
        sm[r][tid] = cb[(size_t)sidx[r] * D_ + tid];
    __syncthreads();

    int tt = tid & 31, dp = tid >> 5;
    double lsum = 0.0;
    #pragma unroll 4
    for (int it = 0; it < 32; it++) {
        int d = dp * 32 + it;
        size_t oi = ((size_t)b * D_ + d) * T_ + t0 + tt;
        float zq = sm[tt][d];
        float zv = z[oi];
        float r  = zq - zv;
        out[oi]  = zv + r;
        lsum += (double)r * r;
    }
    #pragma unroll
    for (int o = 16; o; o >>= 1) lsum += __shfl_xor_sync(0xffffffffu, lsum, o);
    if (tt == 0) ssum[dp] = lsum;
    __syncthreads();
    if (tid == 0) {
        double tot = 0.0;
        #pragma unroll
        for (int p = 0; p < 8; p++) tot += ssum[p];
        atomicAdd(&g_loss, tot);
    }
}

__global__ void finalize_kernel(float* __restrict__ out, int out_size) {
    if (out_size >= ZQ_ELEMS + BT_ + 1)
        out[ZQ_ELEMS + BT_] = (float)(1.1 * g_loss / (double)ZQ_ELEMS);
}

// ---------------- launch ----------------
extern "C" void kernel_launch(void* const* d_in, const int* in_sizes, int n_in,
                              void* d_out, int out_size) {
    const float* z  = (const float*)d_in[0];
    const float* cb = (const float*)d_in[1];
    if (n_in >= 2 && in_sizes[0] == K_ * D_ && in_sizes[1] == ZQ_ELEMS) {
        const float* t = z; z = cb; cb = t;
    }
    float* out = (float*)d_out;

    cudaFuncSetAttribute(dist_mma_kernel,
                         cudaFuncAttributeMaxDynamicSharedMemorySize, SMEM_BYTES);

    init_kernel<<<(BT_ + 255) / 256, 256>>>();
    split_cb_kernel<<<K_ / 8, 256>>>(cb);
    split_z_kernel<<<BT_ / 32, 256>>>(z);

    dim3 grid(K_ / 128, BT_ / 128);   // (64, 128)
    dist_mma_kernel<<<grid, 256, SMEM_BYTES>>>();

    gather_kernel<<<BT_ / 32, 256>>>(z, cb, out, out_size);
    finalize_kernel<<<1, 1>>>(out, out_size);
}